// round 12
// baseline (speedup 1.0000x reference)
#include <cuda_runtime.h>
#include <cuda_fp16.h>
#include <cstdint>
#include <cstddef>

#define BB 4
#define SS 2048
#define DD 512
#define HH 8
#define DH 64
#define MTOT (BB * SS)

// softmax scale folded with log2(e): scores_log2 = (Q*SCL) . K
#define SCL 0.18033688011112042f   // (1/8) * log2(e)

// ---------------------------------------------------------------------------
// Scratch (allocation-free rule: __device__ globals). All fp16 split pairs.
// ---------------------------------------------------------------------------
__device__ __half g_xh[MTOT * DD], g_xl[MTOT * DD];
__device__ __half g_qh[MTOT * DD], g_ql[MTOT * DD];
__device__ __half g_kh[MTOT * DD], g_kl[MTOT * DD];
__device__ __half g_vh[MTOT * DD], g_vl[MTOT * DD];
__device__ __half g_ah[MTOT * DD], g_al[MTOT * DD];
__device__ __half g_wqh[DD * DD], g_wql[DD * DD];
__device__ __half g_wkh[DD * DD], g_wkl[DD * DD];
__device__ __half g_wvh[DD * DD], g_wvl[DD * DD];
__device__ __half g_woh[DD * DD], g_wol[DD * DD];

// ===========================================================================
// helpers
// ===========================================================================
__device__ __forceinline__ uint32_t smem_u32(const void* p) {
    uint32_t a;
    asm("{ .reg .u64 t; cvta.to.shared.u64 t, %1; cvt.u32.u64 %0, t; }"
        : "=r"(a) : "l"(p));
    return a;
}

__device__ __forceinline__ void ldsm4(uint32_t* r, uint32_t addr) {
    asm volatile("ldmatrix.sync.aligned.m8n8.x4.shared.b16 {%0,%1,%2,%3}, [%4];"
        : "=r"(r[0]), "=r"(r[1]), "=r"(r[2]), "=r"(r[3]) : "r"(addr));
}
__device__ __forceinline__ void ldsm4t(uint32_t* r, uint32_t addr) {
    asm volatile("ldmatrix.sync.aligned.m8n8.x4.trans.shared.b16 {%0,%1,%2,%3}, [%4];"
        : "=r"(r[0]), "=r"(r[1]), "=r"(r[2]), "=r"(r[3]) : "r"(addr));
}

__device__ __forceinline__ void mma_f16(float* c, const uint32_t* a,
                                        uint32_t b0, uint32_t b1) {
    asm volatile(
        "mma.sync.aligned.m16n8k16.row.col.f32.f16.f16.f32 "
        "{%0,%1,%2,%3}, {%4,%5,%6,%7}, {%8,%9}, {%0,%1,%2,%3};"
        : "+f"(c[0]), "+f"(c[1]), "+f"(c[2]), "+f"(c[3])
        : "r"(a[0]), "r"(a[1]), "r"(a[2]), "r"(a[3]), "r"(b0), "r"(b1));
}

__device__ __forceinline__ void cp16(uint32_t dst, const void* src) {
    asm volatile("cp.async.cg.shared.global [%0], [%1], 16;"
                 :: "r"(dst), "l"(src));
}
__device__ __forceinline__ void cp_commit() {
    asm volatile("cp.async.commit_group;" ::: "memory");
}
template <int N>
__device__ __forceinline__ void cp_wait() {
    asm volatile("cp.async.wait_group %0;" :: "n"(N) : "memory");
}

__device__ __forceinline__ uint32_t h2u(__half2 h) {
    return *reinterpret_cast<uint32_t*>(&h);
}

// 2^x via degree-4 poly on FMA pipe.
__device__ __forceinline__ float fexp2(float x) {
    x = fmaxf(x, -125.0f);
    float n = rintf(x);
    float f = x - n;
    float p = 0.00961812910f;
    p = fmaf(p, f, 0.0555041087f);
    p = fmaf(p, f, 0.240226507f);
    p = fmaf(p, f, 0.693147180f);
    p = fmaf(p, f, 1.0f);
    int e = (int)n;
    return p * __int_as_float((e + 127) << 23);
}

// ===========================================================================
// prep: fp32 -> (hi, lo) fp16 split
// ===========================================================================
__global__ void split_kernel(const float* __restrict__ src,
                             __half* __restrict__ hi, __half* __restrict__ lo,
                             int n4)
{
    int i = blockIdx.x * blockDim.x + threadIdx.x;
    if (i >= n4) return;
    float4 v = ((const float4*)src)[i];
    __half2 a = __floats2half2_rn(v.x, v.y);
    __half2 b = __floats2half2_rn(v.z, v.w);
    float2 fa = __half22float2(a), fb = __half22float2(b);
    __half2 la = __floats2half2_rn(v.x - fa.x, v.y - fa.y);
    __half2 lb = __floats2half2_rn(v.z - fb.x, v.w - fb.y);
    ((__half2*)hi)[2 * i] = a;  ((__half2*)hi)[2 * i + 1] = b;
    ((__half2*)lo)[2 * i] = la; ((__half2*)lo)[2 * i + 1] = lb;
}

// ===========================================================================
// Split-fp16 tensor GEMM (precomputed splits + cp.async double buffer)
// C[M,N] = A@W^T + bias. CTA 128x128, chunk 32, 256 thr (2x4 warps, 64x32).
// Stage regions per buffer: AH 0, AL 14336, WH 28672, WL 43008 (57344 total).
// ===========================================================================
#define GSTR 56
#define GBUF 57344u
#define GEMM_SMEM (2 * 57344)

__device__ __forceinline__ void gemm_stage(
    uint32_t sbase, const __half* Ah, const __half* Al,
    const __half* Wh, const __half* Wl, int bm, int bn, int c, int tid)
{
    // 2048 cp16: 4 arrays x 128 rows x 4 segs (chunk = 32 halves = 4 x 16B)
#pragma unroll
    for (int i = 0; i < 8; i++) {
        const int idx = tid + i * 256;       // 0..2047
        const int arr = idx >> 9;            // 0:Ah 1:Al 2:Wh 3:Wl
        const int r = (idx >> 2) & 127;
        const int seg = idx & 3;
        const __half* base = (arr & 2) ? ((arr & 1) ? Wl : Wh)
                                       : ((arr & 1) ? Al : Ah);
        const int rowb = (arr & 2) ? bn : bm;
        const __half* src = base + (size_t)(rowb + r) * 512 + c * 32 + seg * 8;
        const uint32_t dst = sbase + (uint32_t)arr * 14336u +
                             (uint32_t)(r * GSTR + seg * 8) * 2;
        cp16(dst, src);
    }
}

template <bool SPLIT_OUT>
__global__ __launch_bounds__(256, 2) void gemm16(
    const __half* __restrict__ Ah, const __half* __restrict__ Al,
    const __half* __restrict__ Wh, const __half* __restrict__ Wl,
    const float* __restrict__ bias, float scale,
    __half* __restrict__ Oh, __half* __restrict__ Ol,
    float* __restrict__ Of)
{
    extern __shared__ char sm[];
    const uint32_t smb = smem_u32(sm);
    const int tid = threadIdx.x, lane = tid & 31, wid = tid >> 5;
    const int wm = wid & 1, wn = wid >> 1;
    const int bm = blockIdx.y * 128, bn = blockIdx.x * 128;

    float acc[4][4][4];
#pragma unroll
    for (int i = 0; i < 4; i++)
#pragma unroll
        for (int j = 0; j < 4; j++)
#pragma unroll
            for (int k = 0; k < 4; k++) acc[i][j][k] = 0.f;

    gemm_stage(smb, Ah, Al, Wh, Wl, bm, bn, 0, tid);
    cp_commit();

#pragma unroll 1
    for (int c = 0; c < 16; c++) {
        const uint32_t bufb = (uint32_t)(c & 1) * GBUF;
        if (c < 15) {
            gemm_stage(smb + (uint32_t)((c + 1) & 1) * GBUF,
                       Ah, Al, Wh, Wl, bm, bn, c + 1, tid);
            cp_commit();
            cp_wait<1>();
        } else {
            cp_wait<0>();
        }
        __syncthreads();

#pragma unroll
        for (int kc = 0; kc < 2; kc++) {
            uint32_t ah[4][4], al[4][4];
#pragma unroll
            for (int mt = 0; mt < 4; mt++) {
                const uint32_t aaddr = smb + bufb +
                    (uint32_t)((wm * 64 + mt * 16 + (lane & 15)) * GSTR +
                               kc * 16 + (lane >> 4) * 8) * 2;
                ldsm4(ah[mt], aaddr);
                ldsm4(al[mt], aaddr + 14336u);
            }
#pragma unroll
            for (int np = 0; np < 2; np++) {
                const uint32_t kaddr = smb + bufb + 28672u +
                    (uint32_t)((wn * 32 + np * 16 + (lane & 7) + ((lane & 16) ? 8 : 0)) * GSTR +
                               kc * 16 + ((lane & 8) ? 8 : 0)) * 2;
                uint32_t bh[4], bl[4];
                ldsm4(bh, kaddr);
                ldsm4(bl, kaddr + 14336u);
#pragma unroll
                for (int mt = 0; mt < 4; mt++) {
                    mma_f16(acc[mt][2 * np], ah[mt], bh[0], bh[1]);
                    mma_f16(acc[mt][2 * np], ah[mt], bl[0], bl[1]);
                    mma_f16(acc[mt][2 * np], al[mt], bh[0], bh[1]);
                    mma_f16(acc[mt][2 * np + 1], ah[mt], bh[2], bh[3]);
                    mma_f16(acc[mt][2 * np + 1], ah[mt], bl[2], bl[3]);
                    mma_f16(acc[mt][2 * np + 1], al[mt], bh[2], bh[3]);
                }
            }
        }
        __syncthreads();
    }

    // epilogue
#pragma unroll
    for (int nt = 0; nt < 4; nt++) {
        const int col = bn + wn * 32 + nt * 8 + 2 * (lane & 3);
        const float b0 = __ldg(bias + col), b1 = __ldg(bias + col + 1);
#pragma unroll
        for (int mt = 0; mt < 4; mt++) {
            const int row = bm + wm * 64 + mt * 16 + (lane >> 2);
            if (SPLIT_OUT) {
                const float f0 = (acc[mt][nt][0] + b0) * scale;
                const float f1 = (acc[mt][nt][1] + b1) * scale;
                const float f2 = (acc[mt][nt][2] + b0) * scale;
                const float f3 = (acc[mt][nt][3] + b1) * scale;
                __half2 h01 = __floats2half2_rn(f0, f1);
                __half2 h23 = __floats2half2_rn(f2, f3);
                float2 a01 = __half22float2(h01), a23 = __half22float2(h23);
                __half2 l01 = __floats2half2_rn(f0 - a01.x, f1 - a01.y);
                __half2 l23 = __floats2half2_rn(f2 - a23.x, f3 - a23.y);
                *(__half2*)(Oh + (size_t)row * 512 + col) = h01;
                *(__half2*)(Ol + (size_t)row * 512 + col) = l01;
                *(__half2*)(Oh + (size_t)(row + 8) * 512 + col) = h23;
                *(__half2*)(Ol + (size_t)(row + 8) * 512 + col) = l23;
            } else {
                float2 v0 = {acc[mt][nt][0] + b0, acc[mt][nt][1] + b1};
                float2 v1 = {acc[mt][nt][2] + b0, acc[mt][nt][3] + b1};
                *(float2*)(Of + (size_t)row * 512 + col) = v0;
                *(float2*)(Of + (size_t)(row + 8) * 512 + col) = v1;
            }
        }
    }
}

// ===========================================================================
// Tensor-core causal flash attention, precomputed splits, cp.async KV pipe.
// BQ=128, BK=64, 256 thr (8 warps x 16 rows). Q pre-scaled by SCL upstream.
// smem: QH 0 (18432), QL 18432; KV stage s at 36864+s*36864:
//       KH +0, KL +9216, VH +18432, VL +27648. Total 110592.
// ===========================================================================
#define ASTR 72
#define AKV0 36864u
#define AKVS 36864u
#define ATTN_SMEM 110592

__device__ __forceinline__ void attn_stage_kv(
    uint32_t sbase, const __half* Kh, const __half* Kl,
    const __half* Vh, const __half* Vl, size_t baseKV, int k0, int tid)
{
    // 2048 cp16: 4 arrays x 64 rows x 8 segs (row = 64 halves = 8 x 16B)
#pragma unroll
    for (int i = 0; i < 8; i++) {
        const int idx = tid + i * 256;       // 0..2047
        const int arr = idx >> 9;            // 0:Kh 1:Kl 2:Vh 3:Vl
        const int r = (idx >> 3) & 63;
        const int seg = idx & 7;
        const __half* base = (arr & 2) ? ((arr & 1) ? Vl : Vh)
                                       : ((arr & 1) ? Kl : Kh);
        const __half* src = base + baseKV + (size_t)(k0 + r) * 512 + seg * 8;
        const uint32_t dst = sbase + (uint32_t)arr * 9216u +
                             (uint32_t)(r * ASTR + seg * 8) * 2;
        cp16(dst, src);
    }
}

__global__ __launch_bounds__(256, 2) void attn_tc(
    const __half* __restrict__ Qh, const __half* __restrict__ Ql,
    const __half* __restrict__ Kh, const __half* __restrict__ Kl,
    const __half* __restrict__ Vh, const __half* __restrict__ Vl,
    __half* __restrict__ Oh, __half* __restrict__ Ol)
{
    extern __shared__ char sm[];
    const uint32_t smb = smem_u32(sm);
    const int tid = threadIdx.x, lane = tid & 31, wid = tid >> 5;
    const int qb = (gridDim.x - 1) - blockIdx.x;   // long blocks first
    const int hd = blockIdx.y, b = blockIdx.z;
    const int q0 = qb * 128;
    const size_t baseQ = ((size_t)b * SS + q0) * DD + hd * DH;
    const size_t baseKV = ((size_t)b * SS) * DD + hd * DH;
    const int row0 = wid * 16;

    // stage Q (hi/lo): 2048 cp16 = 2 arrays x 128 rows x 8 segs
#pragma unroll
    for (int i = 0; i < 8; i++) {
        const int idx = tid + i * 256;       // 0..2047
        const int arr = idx >> 10;           // 0:Qh 1:Ql
        const int r = (idx >> 3) & 127;
        const int seg = idx & 7;
        const __half* src = (arr ? Ql : Qh) + baseQ + (size_t)r * 512 + seg * 8;
        const uint32_t dst = smb + (uint32_t)arr * 18432u +
                             (uint32_t)(r * ASTR + seg * 8) * 2;
        cp16(dst, src);
    }
    attn_stage_kv(smb + AKV0, Kh, Kl, Vh, Vl, baseKV, 0, tid);
    cp_commit();

    float o[8][4];
#pragma unroll
    for (int i = 0; i < 8; i++)
#pragma unroll
        for (int j = 0; j < 4; j++) o[i][j] = 0.f;
    float m0 = -1e30f, m1 = -1e30f, l0 = 0.f, l1 = 0.f;

    const int kbmax = 2 * qb + 1;
#pragma unroll 1
    for (int kb = 0; kb <= kbmax; kb++) {
        const int k0 = kb * 64;
        const uint32_t kvb = smb + AKV0 + (uint32_t)(kb & 1) * AKVS;
        if (kb < kbmax) {
            attn_stage_kv(smb + AKV0 + (uint32_t)((kb + 1) & 1) * AKVS,
                          Kh, Kl, Vh, Vl, baseKV, k0 + 64, tid);
            cp_commit();
            cp_wait<1>();
        } else {
            cp_wait<0>();
        }
        __syncthreads();

        // ---- scores S = (Q*SCL) K^T, 3-product split ----
        float s[8][4];
#pragma unroll
        for (int i = 0; i < 8; i++)
#pragma unroll
            for (int j = 0; j < 4; j++) s[i][j] = 0.f;
#pragma unroll
        for (int kc = 0; kc < 4; kc++) {
            uint32_t qfh[4], qfl[4];
            const uint32_t qaddr = smb +
                (uint32_t)((row0 + (lane & 15)) * ASTR + kc * 16 + (lane >> 4) * 8) * 2;
            ldsm4(qfh, qaddr);
            ldsm4(qfl, qaddr + 18432u);
#pragma unroll
            for (int np = 0; np < 4; np++) {
                const uint32_t kaddr = kvb +
                    (uint32_t)((np * 16 + (lane & 7) + ((lane & 16) ? 8 : 0)) * ASTR +
                               kc * 16 + ((lane & 8) ? 8 : 0)) * 2;
                uint32_t bh[4], bl[4];
                ldsm4(bh, kaddr);
                ldsm4(bl, kaddr + 9216u);
                mma_f16(s[2 * np], qfh, bh[0], bh[1]);
                mma_f16(s[2 * np], qfh, bl[0], bl[1]);
                mma_f16(s[2 * np], qfl, bh[0], bh[1]);
                mma_f16(s[2 * np + 1], qfh, bh[2], bh[3]);
                mma_f16(s[2 * np + 1], qfh, bl[2], bl[3]);
                mma_f16(s[2 * np + 1], qfl, bh[2], bh[3]);
            }
        }

        // ---- causal mask ----
        if (kb >= 2 * qb) {
            const int qr = q0 + row0 + (lane >> 2);
#pragma unroll
            for (int nt = 0; nt < 8; nt++) {
                const int cc = k0 + nt * 8 + 2 * (lane & 3);
                if (cc > qr)         s[nt][0] = -1e30f;
                if (cc + 1 > qr)     s[nt][1] = -1e30f;
                if (cc > qr + 8)     s[nt][2] = -1e30f;
                if (cc + 1 > qr + 8) s[nt][3] = -1e30f;
            }
        }

        // ---- online softmax on fragments (log2 domain) ----
        float mx0 = -1e30f, mx1 = -1e30f;
#pragma unroll
        for (int nt = 0; nt < 8; nt++) {
            mx0 = fmaxf(mx0, fmaxf(s[nt][0], s[nt][1]));
            mx1 = fmaxf(mx1, fmaxf(s[nt][2], s[nt][3]));
        }
        mx0 = fmaxf(mx0, __shfl_xor_sync(0xffffffffu, mx0, 1));
        mx0 = fmaxf(mx0, __shfl_xor_sync(0xffffffffu, mx0, 2));
        mx1 = fmaxf(mx1, __shfl_xor_sync(0xffffffffu, mx1, 1));
        mx1 = fmaxf(mx1, __shfl_xor_sync(0xffffffffu, mx1, 2));
        const float mn0 = fmaxf(m0, mx0), mn1 = fmaxf(m1, mx1);
        const float a0 = fexp2(m0 - mn0), a1 = fexp2(m1 - mn1);
        m0 = mn0; m1 = mn1;
        float rs0 = 0.f, rs1 = 0.f;
#pragma unroll
        for (int nt = 0; nt < 8; nt++) {
            s[nt][0] = fexp2(s[nt][0] - mn0);
            s[nt][1] = fexp2(s[nt][1] - mn0);
            s[nt][2] = fexp2(s[nt][2] - mn1);
            s[nt][3] = fexp2(s[nt][3] - mn1);
            rs0 += s[nt][0] + s[nt][1];
            rs1 += s[nt][2] + s[nt][3];
        }
        rs0 += __shfl_xor_sync(0xffffffffu, rs0, 1);
        rs0 += __shfl_xor_sync(0xffffffffu, rs0, 2);
        rs1 += __shfl_xor_sync(0xffffffffu, rs1, 1);
        rs1 += __shfl_xor_sync(0xffffffffu, rs1, 2);
        l0 = l0 * a0 + rs0;
        l1 = l1 * a1 + rs1;
#pragma unroll
        for (int nt = 0; nt < 8; nt++) {
            o[nt][0] *= a0; o[nt][1] *= a0;
            o[nt][2] *= a1; o[nt][3] *= a1;
        }

        // ---- PV: P x V (trans ldmatrix, split V) ----
#pragma unroll
        for (int kc = 0; kc < 4; kc++) {
            uint32_t pa[4];
            pa[0] = h2u(__floats2half2_rn(s[2 * kc][0], s[2 * kc][1]));
            pa[1] = h2u(__floats2half2_rn(s[2 * kc][2], s[2 * kc][3]));
            pa[2] = h2u(__floats2half2_rn(s[2 * kc + 1][0], s[2 * kc + 1][1]));
            pa[3] = h2u(__floats2half2_rn(s[2 * kc + 1][2], s[2 * kc + 1][3]));
#pragma unroll
            for (int np = 0; np < 4; np++) {
                const uint32_t vaddr = kvb + 18432u +
                    (uint32_t)((kc * 16 + (lane & 15)) * ASTR + np * 16 + (lane >> 4) * 8) * 2;
                uint32_t vfh[4], vfl[4];
                ldsm4t(vfh, vaddr);
                ldsm4t(vfl, vaddr + 9216u);
                mma_f16(o[2 * np], pa, vfh[0], vfh[1]);
                mma_f16(o[2 * np], pa, vfl[0], vfl[1]);
                mma_f16(o[2 * np + 1], pa, vfh[2], vfh[3]);
                mma_f16(o[2 * np + 1], pa, vfl[2], vfl[3]);
            }
        }
        __syncthreads();
    }

    // epilogue: normalize, split-fp16 out (feeds O-projection GEMM)
    const float i0 = 1.f / l0, i1 = 1.f / l1;
    const int r0 = q0 + row0 + (lane >> 2);
#pragma unroll
    for (int nt = 0; nt < 8; nt++) {
        const int d = nt * 8 + 2 * (lane & 3);
        const float f0 = o[nt][0] * i0, f1 = o[nt][1] * i0;
        const float f2 = o[nt][2] * i1, f3 = o[nt][3] * i1;
        __half2 h01 = __floats2half2_rn(f0, f1);
        __half2 h23 = __floats2half2_rn(f2, f3);
        float2 a01 = __half22float2(h01), a23 = __half22float2(h23);
        __half2 l01 = __floats2half2_rn(f0 - a01.x, f1 - a01.y);
        __half2 l23 = __floats2half2_rn(f2 - a23.x, f3 - a23.y);
        const size_t off0 = ((size_t)b * SS + r0) * DD + hd * DH + d;
        const size_t off1 = ((size_t)b * SS + r0 + 8) * DD + hd * DH + d;
        *(__half2*)(Oh + off0) = h01;
        *(__half2*)(Ol + off0) = l01;
        *(__half2*)(Oh + off1) = h23;
        *(__half2*)(Ol + off1) = l23;
    }
}

// ===========================================================================
extern "C" void kernel_launch(void* const* d_in, const int* in_sizes, int n_in,
                              void* d_out, int out_size)
{
    const float* x  = (const float*)d_in[0];
    // d_in[1] = causal mask (implicit)
    const float* WQ = (const float*)d_in[2];
    const float* bQ = (const float*)d_in[3];
    const float* WK = (const float*)d_in[4];
    const float* bK = (const float*)d_in[5];
    const float* WV = (const float*)d_in[6];
    const float* bV = (const float*)d_in[7];
    const float* WO = (const float*)d_in[8];
    const float* bO = (const float*)d_in[9];
    float* out = (float*)d_out;

    __half *xh, *xl, *qh, *ql, *kh, *kl, *vh, *vl, *ah, *al;
    __half *wqh, *wql, *wkh, *wkl, *wvh, *wvl, *woh, *wol;
    cudaGetSymbolAddress((void**)&xh, g_xh);  cudaGetSymbolAddress((void**)&xl, g_xl);
    cudaGetSymbolAddress((void**)&qh, g_qh);  cudaGetSymbolAddress((void**)&ql, g_ql);
    cudaGetSymbolAddress((void**)&kh, g_kh);  cudaGetSymbolAddress((void**)&kl, g_kl);
    cudaGetSymbolAddress((void**)&vh, g_vh);  cudaGetSymbolAddress((void**)&vl, g_vl);
    cudaGetSymbolAddress((void**)&ah, g_ah);  cudaGetSymbolAddress((void**)&al, g_al);
    cudaGetSymbolAddress((void**)&wqh, g_wqh); cudaGetSymbolAddress((void**)&wql, g_wql);
    cudaGetSymbolAddress((void**)&wkh, g_wkh); cudaGetSymbolAddress((void**)&wkl, g_wkl);
    cudaGetSymbolAddress((void**)&wvh, g_wvh); cudaGetSymbolAddress((void**)&wvl, g_wvl);
    cudaGetSymbolAddress((void**)&woh, g_woh); cudaGetSymbolAddress((void**)&wol, g_wol);

    cudaFuncSetAttribute(gemm16<true>,
                         cudaFuncAttributeMaxDynamicSharedMemorySize, GEMM_SMEM);
    cudaFuncSetAttribute(gemm16<false>,
                         cudaFuncAttributeMaxDynamicSharedMemorySize, GEMM_SMEM);
    cudaFuncSetAttribute(attn_tc,
                         cudaFuncAttributeMaxDynamicSharedMemorySize, ATTN_SMEM);

    const int n4x = MTOT * DD / 4;
    const int n4w = DD * DD / 4;
    split_kernel<<<(n4x + 255) / 256, 256>>>(x, xh, xl, n4x);
    split_kernel<<<(n4w + 255) / 256, 256>>>(WQ, wqh, wql, n4w);
    split_kernel<<<(n4w + 255) / 256, 256>>>(WK, wkh, wkl, n4w);
    split_kernel<<<(n4w + 255) / 256, 256>>>(WV, wvh, wvl, n4w);
    split_kernel<<<(n4w + 255) / 256, 256>>>(WO, woh, wol, n4w);

    dim3 gg(DD / 128, MTOT / 128);   // (4, 64)
    gemm16<true><<<gg, 256, GEMM_SMEM>>>(xh, xl, wqh, wql, bQ, SCL, qh, ql, nullptr);
    gemm16<true><<<gg, 256, GEMM_SMEM>>>(xh, xl, wkh, wkl, bK, 1.f, kh, kl, nullptr);
    gemm16<true><<<gg, 256, GEMM_SMEM>>>(xh, xl, wvh, wvl, bV, 1.f, vh, vl, nullptr);
    attn_tc<<<dim3(SS / 128, HH, BB), 256, ATTN_SMEM>>>(qh, ql, kh, kl, vh, vl, ah, al);
    gemm16<false><<<gg, 256, GEMM_SMEM>>>(ah, al, woh, wol, bO, 1.f,
                                          nullptr, nullptr, out);
}

// round 14
// speedup vs baseline: 1.2357x; 1.2357x over previous
#include <cuda_runtime.h>
#include <cuda_fp16.h>
#include <cstdint>
#include <cstddef>

#define BB 4
#define SS 2048
#define DD 512
#define HH 8
#define DH 64
#define MTOT (BB * SS)

// softmax scale folded with log2(e): scores_log2 = (Q*SCL) . K
#define SCL 0.18033688011112042f   // (1/8) * log2(e)

// ---------------------------------------------------------------------------
// Scratch (allocation-free rule: __device__ globals). fp16 split pairs.
// ---------------------------------------------------------------------------
__device__ __half g_xh[MTOT * DD], g_xl[MTOT * DD];
__device__ __half g_qh[MTOT * DD], g_ql[MTOT * DD];
__device__ __half g_kh[MTOT * DD], g_kl[MTOT * DD];
__device__ __half g_vh[MTOT * DD], g_vl[MTOT * DD];
__device__ __half g_ah[MTOT * DD], g_al[MTOT * DD];
__device__ __half g_wqh[DD * DD], g_wql[DD * DD];
__device__ __half g_wkh[DD * DD], g_wkl[DD * DD];
__device__ __half g_wvh[DD * DD], g_wvl[DD * DD];
__device__ __half g_woh[DD * DD], g_wol[DD * DD];

// ===========================================================================
// helpers
// ===========================================================================
__device__ __forceinline__ uint32_t smem_u32(const void* p) {
    uint32_t a;
    asm("{ .reg .u64 t; cvta.to.shared.u64 t, %1; cvt.u32.u64 %0, t; }"
        : "=r"(a) : "l"(p));
    return a;
}

__device__ __forceinline__ void ldsm4(uint32_t* r, uint32_t addr) {
    asm volatile("ldmatrix.sync.aligned.m8n8.x4.shared.b16 {%0,%1,%2,%3}, [%4];"
        : "=r"(r[0]), "=r"(r[1]), "=r"(r[2]), "=r"(r[3]) : "r"(addr));
}
__device__ __forceinline__ void ldsm4t(uint32_t* r, uint32_t addr) {
    asm volatile("ldmatrix.sync.aligned.m8n8.x4.trans.shared.b16 {%0,%1,%2,%3}, [%4];"
        : "=r"(r[0]), "=r"(r[1]), "=r"(r[2]), "=r"(r[3]) : "r"(addr));
}

__device__ __forceinline__ void mma_f16(float* c, const uint32_t* a,
                                        uint32_t b0, uint32_t b1) {
    asm volatile(
        "mma.sync.aligned.m16n8k16.row.col.f32.f16.f16.f32 "
        "{%0,%1,%2,%3}, {%4,%5,%6,%7}, {%8,%9}, {%0,%1,%2,%3};"
        : "+f"(c[0]), "+f"(c[1]), "+f"(c[2]), "+f"(c[3])
        : "r"(a[0]), "r"(a[1]), "r"(a[2]), "r"(a[3]), "r"(b0), "r"(b1));
}

__device__ __forceinline__ void cp16(uint32_t dst, const void* src) {
    asm volatile("cp.async.cg.shared.global [%0], [%1], 16;"
                 :: "r"(dst), "l"(src));
}
__device__ __forceinline__ void cp_commit() {
    asm volatile("cp.async.commit_group;" ::: "memory");
}
template <int N>
__device__ __forceinline__ void cp_wait() {
    asm volatile("cp.async.wait_group %0;" :: "n"(N) : "memory");
}

__device__ __forceinline__ uint32_t h2u(__half2 h) {
    return *reinterpret_cast<uint32_t*>(&h);
}

// 2^x via degree-4 poly on FMA pipe.
__device__ __forceinline__ float fexp2(float x) {
    x = fmaxf(x, -125.0f);
    float n = rintf(x);
    float f = x - n;
    float p = 0.00961812910f;
    p = fmaf(p, f, 0.0555041087f);
    p = fmaf(p, f, 0.240226507f);
    p = fmaf(p, f, 0.693147180f);
    p = fmaf(p, f, 1.0f);
    int e = (int)n;
    return p * __int_as_float((e + 127) << 23);
}

// ===========================================================================
// prep: fp32 -> (hi, lo) fp16 split for x + all 4 weights, one launch
// ===========================================================================
#define N4X (MTOT * DD / 4)
#define N4W (DD * DD / 4)

__global__ void split_all(
    const float* __restrict__ x,
    const float* __restrict__ WQ, const float* __restrict__ WK,
    const float* __restrict__ WV, const float* __restrict__ WO,
    __half* __restrict__ xh, __half* __restrict__ xl,
    __half* __restrict__ wqh, __half* __restrict__ wql,
    __half* __restrict__ wkh, __half* __restrict__ wkl,
    __half* __restrict__ wvh, __half* __restrict__ wvl,
    __half* __restrict__ woh, __half* __restrict__ wol)
{
    const int i = blockIdx.x * blockDim.x + threadIdx.x;
    const float* src;
    __half *hi, *lo;
    int off;
    if (i < N4X) {
        src = x; hi = xh; lo = xl; off = i;
    } else {
        const int j = i - N4X;
        const int w = j >> 16;            // N4W == 65536
        off = j & 65535;
        if (w == 0)      { src = WQ; hi = wqh; lo = wql; }
        else if (w == 1) { src = WK; hi = wkh; lo = wkl; }
        else if (w == 2) { src = WV; hi = wvh; lo = wvl; }
        else             { src = WO; hi = woh; lo = wol; }
    }
    float4 v = ((const float4*)src)[off];
    __half2 a = __floats2half2_rn(v.x, v.y);
    __half2 b = __floats2half2_rn(v.z, v.w);
    float2 fa = __half22float2(a), fb = __half22float2(b);
    __half2 la = __floats2half2_rn(v.x - fa.x, v.y - fa.y);
    __half2 lb = __floats2half2_rn(v.z - fb.x, v.w - fb.y);
    ((__half2*)hi)[2 * off] = a;  ((__half2*)hi)[2 * off + 1] = b;
    ((__half2*)lo)[2 * off] = la; ((__half2*)lo)[2 * off + 1] = lb;
}

// ===========================================================================
// Split-fp16 tensor GEMM (3-product, cp.async double buffer)
// C[M,N] = A@W^T + bias. CTA 128x128, chunk 32, 256 thr (2x4 warps, 64x32).
// Stage regions per buffer: AH 0, AL 14336, WH 28672, WL 43008 (57344 total).
// ===========================================================================
#define GSTR 56
#define GBUF 57344u
#define GEMM_SMEM (2 * 57344)

__device__ __forceinline__ void gemm_stage(
    uint32_t sbase, const __half* Ah, const __half* Al,
    const __half* Wh, const __half* Wl, int bm, int bn, int c, int tid)
{
#pragma unroll
    for (int i = 0; i < 8; i++) {
        const int idx = tid + i * 256;       // 0..2047
        const int arr = idx >> 9;            // 0:Ah 1:Al 2:Wh 3:Wl
        const int r = (idx >> 2) & 127;
        const int seg = idx & 3;
        const __half* base = (arr & 2) ? ((arr & 1) ? Wl : Wh)
                                       : ((arr & 1) ? Al : Ah);
        const int rowb = (arr & 2) ? bn : bm;
        const __half* src = base + (size_t)(rowb + r) * 512 + c * 32 + seg * 8;
        const uint32_t dst = sbase + (uint32_t)arr * 14336u +
                             (uint32_t)(r * GSTR + seg * 8) * 2;
        cp16(dst, src);
    }
}

template <bool SPLIT_OUT>
__global__ __launch_bounds__(256, 2) void gemm16(
    const __half* __restrict__ Ah, const __half* __restrict__ Al,
    const __half* __restrict__ Wh, const __half* __restrict__ Wl,
    const float* __restrict__ bias, float scale,
    __half* __restrict__ Oh, __half* __restrict__ Ol,
    float* __restrict__ Of)
{
    extern __shared__ char sm[];
    const uint32_t smb = smem_u32(sm);
    const int tid = threadIdx.x, lane = tid & 31, wid = tid >> 5;
    const int wm = wid & 1, wn = wid >> 1;
    const int bm = blockIdx.y * 128, bn = blockIdx.x * 128;

    float acc[4][4][4];
#pragma unroll
    for (int i = 0; i < 4; i++)
#pragma unroll
        for (int j = 0; j < 4; j++)
#pragma unroll
            for (int k = 0; k < 4; k++) acc[i][j][k] = 0.f;

    gemm_stage(smb, Ah, Al, Wh, Wl, bm, bn, 0, tid);
    cp_commit();

#pragma unroll 1
    for (int c = 0; c < 16; c++) {
        const uint32_t bufb = (uint32_t)(c & 1) * GBUF;
        if (c < 15) {
            gemm_stage(smb + (uint32_t)((c + 1) & 1) * GBUF,
                       Ah, Al, Wh, Wl, bm, bn, c + 1, tid);
            cp_commit();
            cp_wait<1>();
        } else {
            cp_wait<0>();
        }
        __syncthreads();

#pragma unroll
        for (int kc = 0; kc < 2; kc++) {
            uint32_t ah[4][4], al[4][4];
#pragma unroll
            for (int mt = 0; mt < 4; mt++) {
                const uint32_t aaddr = smb + bufb +
                    (uint32_t)((wm * 64 + mt * 16 + (lane & 15)) * GSTR +
                               kc * 16 + (lane >> 4) * 8) * 2;
                ldsm4(ah[mt], aaddr);
                ldsm4(al[mt], aaddr + 14336u);
            }
#pragma unroll
            for (int np = 0; np < 2; np++) {
                const uint32_t kaddr = smb + bufb + 28672u +
                    (uint32_t)((wn * 32 + np * 16 + (lane & 7) + ((lane & 16) ? 8 : 0)) * GSTR +
                               kc * 16 + ((lane & 8) ? 8 : 0)) * 2;
                uint32_t bh[4], bl[4];
                ldsm4(bh, kaddr);
                ldsm4(bl, kaddr + 14336u);
#pragma unroll
                for (int mt = 0; mt < 4; mt++) {
                    mma_f16(acc[mt][2 * np], ah[mt], bh[0], bh[1]);
                    mma_f16(acc[mt][2 * np], ah[mt], bl[0], bl[1]);
                    mma_f16(acc[mt][2 * np], al[mt], bh[0], bh[1]);
                    mma_f16(acc[mt][2 * np + 1], ah[mt], bh[2], bh[3]);
                    mma_f16(acc[mt][2 * np + 1], ah[mt], bl[2], bl[3]);
                    mma_f16(acc[mt][2 * np + 1], al[mt], bh[2], bh[3]);
                }
            }
        }
        __syncthreads();
    }

    // epilogue
#pragma unroll
    for (int nt = 0; nt < 4; nt++) {
        const int col = bn + wn * 32 + nt * 8 + 2 * (lane & 3);
        const float b0 = __ldg(bias + col), b1 = __ldg(bias + col + 1);
#pragma unroll
        for (int mt = 0; mt < 4; mt++) {
            const int row = bm + wm * 64 + mt * 16 + (lane >> 2);
            if (SPLIT_OUT) {
                const float f0 = (acc[mt][nt][0] + b0) * scale;
                const float f1 = (acc[mt][nt][1] + b1) * scale;
                const float f2 = (acc[mt][nt][2] + b0) * scale;
                const float f3 = (acc[mt][nt][3] + b1) * scale;
                __half2 h01 = __floats2half2_rn(f0, f1);
                __half2 h23 = __floats2half2_rn(f2, f3);
                float2 a01 = __half22float2(h01), a23 = __half22float2(h23);
                __half2 l01 = __floats2half2_rn(f0 - a01.x, f1 - a01.y);
                __half2 l23 = __floats2half2_rn(f2 - a23.x, f3 - a23.y);
                *(__half2*)(Oh + (size_t)row * 512 + col) = h01;
                *(__half2*)(Ol + (size_t)row * 512 + col) = l01;
                *(__half2*)(Oh + (size_t)(row + 8) * 512 + col) = h23;
                *(__half2*)(Ol + (size_t)(row + 8) * 512 + col) = l23;
            } else {
                float2 v0 = {acc[mt][nt][0] + b0, acc[mt][nt][1] + b1};
                float2 v1 = {acc[mt][nt][2] + b0, acc[mt][nt][3] + b1};
                *(float2*)(Of + (size_t)row * 512 + col) = v0;
                *(float2*)(Of + (size_t)(row + 8) * 512 + col) = v1;
            }
        }
    }
}

// ===========================================================================
// Tensor-core causal flash attention.
// QK^T: 2-product (Q hi+lo split x K-hi). PV: 1-product (P x V-hi).
// BQ=128, BK=64, 256 thr (8 warps x 16 rows). Q pre-scaled by SCL upstream.
// smem: QH 0 (18432), QL 18432; KV stage s at 36864+s*18432:
//       KH +0, VH +9216. Total 73728.
// ===========================================================================
#define ASTR 72
#define AKV0 36864u
#define AKVS 18432u
#define ATTN_SMEM 73728

__device__ __forceinline__ void attn_stage_kv(
    uint32_t sbase, const __half* Kh, const __half* Vh,
    size_t baseKV, int k0, int tid)
{
    // 1024 cp16: 2 arrays x 64 rows x 8 segs (row = 64 halves = 8 x 16B)
#pragma unroll
    for (int i = 0; i < 4; i++) {
        const int idx = tid + i * 256;       // 0..1023
        const int arr = idx >> 9;            // 0:Kh 1:Vh
        const int r = (idx >> 3) & 63;
        const int seg = idx & 7;
        const __half* base = arr ? Vh : Kh;
        const __half* src = base + baseKV + (size_t)(k0 + r) * 512 + seg * 8;
        const uint32_t dst = sbase + (uint32_t)arr * 9216u +
                             (uint32_t)(r * ASTR + seg * 8) * 2;
        cp16(dst, src);
    }
}

__global__ __launch_bounds__(256, 2) void attn_tc(
    const __half* __restrict__ Qh, const __half* __restrict__ Ql,
    const __half* __restrict__ Kh, const __half* __restrict__ Vh,
    __half* __restrict__ Oh, __half* __restrict__ Ol)
{
    extern __shared__ char sm[];
    const uint32_t smb = smem_u32(sm);
    const int tid = threadIdx.x, lane = tid & 31, wid = tid >> 5;
    const int qb = (gridDim.x - 1) - blockIdx.x;   // long blocks first
    const int hd = blockIdx.y, b = blockIdx.z;
    const int q0 = qb * 128;
    const size_t baseQ = ((size_t)b * SS + q0) * DD + hd * DH;
    const size_t baseKV = ((size_t)b * SS) * DD + hd * DH;
    const int row0 = wid * 16;

    // stage Q (hi/lo): 2048 cp16 = 2 arrays x 128 rows x 8 segs
#pragma unroll
    for (int i = 0; i < 8; i++) {
        const int idx = tid + i * 256;       // 0..2047
        const int arr = idx >> 10;           // 0:Qh 1:Ql
        const int r = (idx >> 3) & 127;
        const int seg = idx & 7;
        const __half* src = (arr ? Ql : Qh) + baseQ + (size_t)r * 512 + seg * 8;
        const uint32_t dst = smb + (uint32_t)arr * 18432u +
                             (uint32_t)(r * ASTR + seg * 8) * 2;
        cp16(dst, src);
    }
    attn_stage_kv(smb + AKV0, Kh, Vh, baseKV, 0, tid);
    cp_commit();

    float o[8][4];
#pragma unroll
    for (int i = 0; i < 8; i++)
#pragma unroll
        for (int j = 0; j < 4; j++) o[i][j] = 0.f;
    float m0 = -1e30f, m1 = -1e30f, l0 = 0.f, l1 = 0.f;

    const int kbmax = 2 * qb + 1;
#pragma unroll 1
    for (int kb = 0; kb <= kbmax; kb++) {
        const int k0 = kb * 64;
        const uint32_t kvb = smb + AKV0 + (uint32_t)(kb & 1) * AKVS;
        if (kb < kbmax) {
            attn_stage_kv(smb + AKV0 + (uint32_t)((kb + 1) & 1) * AKVS,
                          Kh, Vh, baseKV, k0 + 64, tid);
            cp_commit();
            cp_wait<1>();
        } else {
            cp_wait<0>();
        }
        __syncthreads();

        // ---- scores S = (Qh+Ql) Kh^T (2-product) ----
        float s[8][4];
#pragma unroll
        for (int i = 0; i < 8; i++)
#pragma unroll
            for (int j = 0; j < 4; j++) s[i][j] = 0.f;
#pragma unroll
        for (int kc = 0; kc < 4; kc++) {
            uint32_t qfh[4], qfl[4];
            const uint32_t qaddr = smb +
                (uint32_t)((row0 + (lane & 15)) * ASTR + kc * 16 + (lane >> 4) * 8) * 2;
            ldsm4(qfh, qaddr);
            ldsm4(qfl, qaddr + 18432u);
#pragma unroll
            for (int np = 0; np < 4; np++) {
                const uint32_t kaddr = kvb +
                    (uint32_t)((np * 16 + (lane & 7) + ((lane & 16) ? 8 : 0)) * ASTR +
                               kc * 16 + ((lane & 8) ? 8 : 0)) * 2;
                uint32_t bh[4];
                ldsm4(bh, kaddr);
                mma_f16(s[2 * np], qfh, bh[0], bh[1]);
                mma_f16(s[2 * np], qfl, bh[0], bh[1]);
                mma_f16(s[2 * np + 1], qfh, bh[2], bh[3]);
                mma_f16(s[2 * np + 1], qfl, bh[2], bh[3]);
            }
        }

        // ---- causal mask ----
        if (kb >= 2 * qb) {
            const int qr = q0 + row0 + (lane >> 2);
#pragma unroll
            for (int nt = 0; nt < 8; nt++) {
                const int cc = k0 + nt * 8 + 2 * (lane & 3);
                if (cc > qr)         s[nt][0] = -1e30f;
                if (cc + 1 > qr)     s[nt][1] = -1e30f;
                if (cc > qr + 8)     s[nt][2] = -1e30f;
                if (cc + 1 > qr + 8) s[nt][3] = -1e30f;
            }
        }

        // ---- online softmax on fragments (log2 domain) ----
        float mx0 = -1e30f, mx1 = -1e30f;
#pragma unroll
        for (int nt = 0; nt < 8; nt++) {
            mx0 = fmaxf(mx0, fmaxf(s[nt][0], s[nt][1]));
            mx1 = fmaxf(mx1, fmaxf(s[nt][2], s[nt][3]));
        }
        mx0 = fmaxf(mx0, __shfl_xor_sync(0xffffffffu, mx0, 1));
        mx0 = fmaxf(mx0, __shfl_xor_sync(0xffffffffu, mx0, 2));
        mx1 = fmaxf(mx1, __shfl_xor_sync(0xffffffffu, mx1, 1));
        mx1 = fmaxf(mx1, __shfl_xor_sync(0xffffffffu, mx1, 2));
        const float mn0 = fmaxf(m0, mx0), mn1 = fmaxf(m1, mx1);
        const float a0 = fexp2(m0 - mn0), a1 = fexp2(m1 - mn1);
        m0 = mn0; m1 = mn1;
        float rs0 = 0.f, rs1 = 0.f;
#pragma unroll
        for (int nt = 0; nt < 8; nt++) {
            s[nt][0] = fexp2(s[nt][0] - mn0);
            s[nt][1] = fexp2(s[nt][1] - mn0);
            s[nt][2] = fexp2(s[nt][2] - mn1);
            s[nt][3] = fexp2(s[nt][3] - mn1);
            rs0 += s[nt][0] + s[nt][1];
            rs1 += s[nt][2] + s[nt][3];
        }
        rs0 += __shfl_xor_sync(0xffffffffu, rs0, 1);
        rs0 += __shfl_xor_sync(0xffffffffu, rs0, 2);
        rs1 += __shfl_xor_sync(0xffffffffu, rs1, 1);
        rs1 += __shfl_xor_sync(0xffffffffu, rs1, 2);
        l0 = l0 * a0 + rs0;
        l1 = l1 * a1 + rs1;
#pragma unroll
        for (int nt = 0; nt < 8; nt++) {
            o[nt][0] *= a0; o[nt][1] *= a0;
            o[nt][2] *= a1; o[nt][3] *= a1;
        }

        // ---- PV: P x V-hi (1-product) ----
#pragma unroll
        for (int kc = 0; kc < 4; kc++) {
            uint32_t pa[4];
            pa[0] = h2u(__floats2half2_rn(s[2 * kc][0], s[2 * kc][1]));
            pa[1] = h2u(__floats2half2_rn(s[2 * kc][2], s[2 * kc][3]));
            pa[2] = h2u(__floats2half2_rn(s[2 * kc + 1][0], s[2 * kc + 1][1]));
            pa[3] = h2u(__floats2half2_rn(s[2 * kc + 1][2], s[2 * kc + 1][3]));
#pragma unroll
            for (int np = 0; np < 4; np++) {
                const uint32_t vaddr = kvb + 9216u +
                    (uint32_t)((kc * 16 + (lane & 15)) * ASTR + np * 16 + (lane >> 4) * 8) * 2;
                uint32_t vfh[4];
                ldsm4t(vfh, vaddr);
                mma_f16(o[2 * np], pa, vfh[0], vfh[1]);
                mma_f16(o[2 * np + 1], pa, vfh[2], vfh[3]);
            }
        }
        __syncthreads();
    }

    // epilogue: normalize, split-fp16 out (feeds O-projection GEMM)
    const float i0 = 1.f / l0, i1 = 1.f / l1;
    const int r0 = q0 + row0 + (lane >> 2);
#pragma unroll
    for (int nt = 0; nt < 8; nt++) {
        const int d = nt * 8 + 2 * (lane & 3);
        const float f0 = o[nt][0] * i0, f1 = o[nt][1] * i0;
        const float f2 = o[nt][2] * i1, f3 = o[nt][3] * i1;
        __half2 h01 = __floats2half2_rn(f0, f1);
        __half2 h23 = __floats2half2_rn(f2, f3);
        float2 a01 = __half22float2(h01), a23 = __half22float2(h23);
        __half2 l01 = __floats2half2_rn(f0 - a01.x, f1 - a01.y);
        __half2 l23 = __floats2half2_rn(f2 - a23.x, f3 - a23.y);
        const size_t off0 = ((size_t)b * SS + r0) * DD + hd * DH + d;
        const size_t off1 = ((size_t)b * SS + r0 + 8) * DD + hd * DH + d;
        *(__half2*)(Oh + off0) = h01;
        *(__half2*)(Ol + off0) = l01;
        *(__half2*)(Oh + off1) = h23;
        *(__half2*)(Ol + off1) = l23;
    }
}

// ===========================================================================
extern "C" void kernel_launch(void* const* d_in, const int* in_sizes, int n_in,
                              void* d_out, int out_size)
{
    const float* x  = (const float*)d_in[0];
    // d_in[1] = causal mask (implicit)
    const float* WQ = (const float*)d_in[2];
    const float* bQ = (const float*)d_in[3];
    const float* WK = (const float*)d_in[4];
    const float* bK = (const float*)d_in[5];
    const float* WV = (const float*)d_in[6];
    const float* bV = (const float*)d_in[7];
    const float* WO = (const float*)d_in[8];
    const float* bO = (const float*)d_in[9];
    float* out = (float*)d_out;

    __half *xh, *xl, *qh, *ql, *kh, *kl, *vh, *vl, *ah, *al;
    __half *wqh, *wql, *wkh, *wkl, *wvh, *wvl, *woh, *wol;
    cudaGetSymbolAddress((void**)&xh, g_xh);  cudaGetSymbolAddress((void**)&xl, g_xl);
    cudaGetSymbolAddress((void**)&qh, g_qh);  cudaGetSymbolAddress((void**)&ql, g_ql);
    cudaGetSymbolAddress((void**)&kh, g_kh);  cudaGetSymbolAddress((void**)&kl, g_kl);
    cudaGetSymbolAddress((void**)&vh, g_vh);  cudaGetSymbolAddress((void**)&vl, g_vl);
    cudaGetSymbolAddress((void**)&ah, g_ah);  cudaGetSymbolAddress((void**)&al, g_al);
    cudaGetSymbolAddress((void**)&wqh, g_wqh); cudaGetSymbolAddress((void**)&wql, g_wql);
    cudaGetSymbolAddress((void**)&wkh, g_wkh); cudaGetSymbolAddress((void**)&wkl, g_wkl);
    cudaGetSymbolAddress((void**)&wvh, g_wvh); cudaGetSymbolAddress((void**)&wvl, g_wvl);
    cudaGetSymbolAddress((void**)&woh, g_woh); cudaGetSymbolAddress((void**)&wol, g_wol);

    cudaFuncSetAttribute(gemm16<true>,
                         cudaFuncAttributeMaxDynamicSharedMemorySize, GEMM_SMEM);
    cudaFuncSetAttribute(gemm16<false>,
                         cudaFuncAttributeMaxDynamicSharedMemorySize, GEMM_SMEM);
    cudaFuncSetAttribute(attn_tc,
                         cudaFuncAttributeMaxDynamicSharedMemorySize, ATTN_SMEM);

    const int ntot = N4X + 4 * N4W;
    split_all<<<(ntot + 255) / 256, 256>>>(x, WQ, WK, WV, WO,
                                           xh, xl, wqh, wql, wkh, wkl,
                                           wvh, wvl, woh, wol);

    dim3 gg(DD / 128, MTOT / 128);   // (4, 64)
    gemm16<true><<<gg, 256, GEMM_SMEM>>>(xh, xl, wqh, wql, bQ, SCL, qh, ql, nullptr);
    gemm16<true><<<gg, 256, GEMM_SMEM>>>(xh, xl, wkh, wkl, bK, 1.f, kh, kl, nullptr);
    gemm16<true><<<gg, 256, GEMM_SMEM>>>(xh, xl, wvh, wvl, bV, 1.f, vh, vl, nullptr);
    attn_tc<<<dim3(SS / 128, HH, BB), 256, ATTN_SMEM>>>(qh, ql, kh, vh, ah, al);
    gemm16<false><<<gg, 256, GEMM_SMEM>>>(ah, al, woh, wol, bO, 1.f,
                                          nullptr, nullptr, out);
}

// round 15
// speedup vs baseline: 1.3738x; 1.1118x over previous
#include <cuda_runtime.h>
#include <cuda_fp16.h>
#include <cstdint>
#include <cstddef>

#define BB 4
#define SS 2048
#define DD 512
#define HH 8
#define DH 64
#define MTOT (BB * SS)

// softmax scale folded with log2(e): scores_log2 = (Q*SCL) . K
#define SCL 0.18033688011112042f   // (1/8) * log2(e)

// ---------------------------------------------------------------------------
// Scratch (allocation-free rule: __device__ globals). fp16 split pairs.
// ---------------------------------------------------------------------------
__device__ __half g_xh[MTOT * DD], g_xl[MTOT * DD];
__device__ __half g_qh[MTOT * DD], g_ql[MTOT * DD];
__device__ __half g_kh[MTOT * DD], g_kl[MTOT * DD];
__device__ __half g_vh[MTOT * DD], g_vl[MTOT * DD];
__device__ __half g_ah[MTOT * DD], g_al[MTOT * DD];
__device__ __half g_wqh[DD * DD], g_wql[DD * DD];
__device__ __half g_wkh[DD * DD], g_wkl[DD * DD];
__device__ __half g_wvh[DD * DD], g_wvl[DD * DD];
__device__ __half g_woh[DD * DD], g_wol[DD * DD];

// ===========================================================================
// helpers
// ===========================================================================
__device__ __forceinline__ uint32_t smem_u32(const void* p) {
    uint32_t a;
    asm("{ .reg .u64 t; cvta.to.shared.u64 t, %1; cvt.u32.u64 %0, t; }"
        : "=r"(a) : "l"(p));
    return a;
}

__device__ __forceinline__ void ldsm4(uint32_t* r, uint32_t addr) {
    asm volatile("ldmatrix.sync.aligned.m8n8.x4.shared.b16 {%0,%1,%2,%3}, [%4];"
        : "=r"(r[0]), "=r"(r[1]), "=r"(r[2]), "=r"(r[3]) : "r"(addr));
}
__device__ __forceinline__ void ldsm4t(uint32_t* r, uint32_t addr) {
    asm volatile("ldmatrix.sync.aligned.m8n8.x4.trans.shared.b16 {%0,%1,%2,%3}, [%4];"
        : "=r"(r[0]), "=r"(r[1]), "=r"(r[2]), "=r"(r[3]) : "r"(addr));
}

__device__ __forceinline__ void mma_f16(float* c, const uint32_t* a,
                                        uint32_t b0, uint32_t b1) {
    asm volatile(
        "mma.sync.aligned.m16n8k16.row.col.f32.f16.f16.f32 "
        "{%0,%1,%2,%3}, {%4,%5,%6,%7}, {%8,%9}, {%0,%1,%2,%3};"
        : "+f"(c[0]), "+f"(c[1]), "+f"(c[2]), "+f"(c[3])
        : "r"(a[0]), "r"(a[1]), "r"(a[2]), "r"(a[3]), "r"(b0), "r"(b1));
}

__device__ __forceinline__ void cp16(uint32_t dst, const void* src) {
    asm volatile("cp.async.cg.shared.global [%0], [%1], 16;"
                 :: "r"(dst), "l"(src));
}
__device__ __forceinline__ void cp_commit() {
    asm volatile("cp.async.commit_group;" ::: "memory");
}
template <int N>
__device__ __forceinline__ void cp_wait() {
    asm volatile("cp.async.wait_group %0;" :: "n"(N) : "memory");
}

__device__ __forceinline__ uint32_t h2u(__half2 h) {
    return *reinterpret_cast<uint32_t*>(&h);
}

// 2^x via degree-4 poly on FMA pipe.
__device__ __forceinline__ float fexp2(float x) {
    x = fmaxf(x, -125.0f);
    float n = rintf(x);
    float f = x - n;
    float p = 0.00961812910f;
    p = fmaf(p, f, 0.0555041087f);
    p = fmaf(p, f, 0.240226507f);
    p = fmaf(p, f, 0.693147180f);
    p = fmaf(p, f, 1.0f);
    int e = (int)n;
    return p * __int_as_float((e + 127) << 23);
}

// ===========================================================================
// prep: fp32 -> (hi, lo) fp16 split for x + all 4 weights, one launch
// ===========================================================================
#define N4X (MTOT * DD / 4)
#define N4W (DD * DD / 4)

__global__ void split_all(
    const float* __restrict__ x,
    const float* __restrict__ WQ, const float* __restrict__ WK,
    const float* __restrict__ WV, const float* __restrict__ WO,
    __half* __restrict__ xh, __half* __restrict__ xl,
    __half* __restrict__ wqh, __half* __restrict__ wql,
    __half* __restrict__ wkh, __half* __restrict__ wkl,
    __half* __restrict__ wvh, __half* __restrict__ wvl,
    __half* __restrict__ woh, __half* __restrict__ wol)
{
    const int i = blockIdx.x * blockDim.x + threadIdx.x;
    const float* src;
    __half *hi, *lo;
    int off;
    if (i < N4X) {
        src = x; hi = xh; lo = xl; off = i;
    } else {
        const int j = i - N4X;
        const int w = j >> 16;            // N4W == 65536
        off = j & 65535;
        if (w == 0)      { src = WQ; hi = wqh; lo = wql; }
        else if (w == 1) { src = WK; hi = wkh; lo = wkl; }
        else if (w == 2) { src = WV; hi = wvh; lo = wvl; }
        else             { src = WO; hi = woh; lo = wol; }
    }
    float4 v = ((const float4*)src)[off];
    __half2 a = __floats2half2_rn(v.x, v.y);
    __half2 b = __floats2half2_rn(v.z, v.w);
    float2 fa = __half22float2(a), fb = __half22float2(b);
    __half2 la = __floats2half2_rn(v.x - fa.x, v.y - fa.y);
    __half2 lb = __floats2half2_rn(v.z - fb.x, v.w - fb.y);
    ((__half2*)hi)[2 * off] = a;  ((__half2*)hi)[2 * off + 1] = b;
    ((__half2*)lo)[2 * off] = la; ((__half2*)lo)[2 * off + 1] = lb;
}

// ===========================================================================
// Split-fp16 tensor GEMM, cp.async double buffer.
// C[M,N] = A@W^T + bias. CTA 128x128, chunk 32, 256 thr (2x4 warps, 64x32).
// USE_WL=true : 3-product (Ah*Wh + Ah*Wl + Al*Wh); regions AH/AL/WH/WL.
// USE_WL=false: 2-product (Ah*Wh + Al*Wh);          regions AH/AL/WH.
// Region stride 14336 (128 rows x 56 halves); buffer = nregions*14336.
// ===========================================================================
#define GSTR 56

template <bool USE_WL>
__device__ __forceinline__ void gemm_stage(
    uint32_t sbase, const __half* Ah, const __half* Al,
    const __half* Wh, const __half* Wl, int bm, int bn, int c, int tid)
{
    const int iters = USE_WL ? 8 : 6;   // (nregions*512)/256
#pragma unroll
    for (int i = 0; i < iters; i++) {
        const int idx = tid + i * 256;
        const int arr = idx >> 9;            // 0:Ah 1:Al 2:Wh 3:Wl
        const int r = (idx >> 2) & 127;
        const int seg = idx & 3;
        const __half* base = (arr & 2) ? ((arr & 1) ? Wl : Wh)
                                       : ((arr & 1) ? Al : Ah);
        const int rowb = (arr & 2) ? bn : bm;
        const __half* src = base + (size_t)(rowb + r) * 512 + c * 32 + seg * 8;
        const uint32_t dst = sbase + (uint32_t)arr * 14336u +
                             (uint32_t)(r * GSTR + seg * 8) * 2;
        cp16(dst, src);
    }
}

template <bool SPLIT_OUT, bool USE_WL>
__global__ __launch_bounds__(256, 2) void gemm16(
    const __half* __restrict__ Ah, const __half* __restrict__ Al,
    const __half* __restrict__ Wh, const __half* __restrict__ Wl,
    const float* __restrict__ bias, float scale,
    __half* __restrict__ Oh, __half* __restrict__ Ol,
    float* __restrict__ Of)
{
    constexpr uint32_t BUFB = USE_WL ? 57344u : 43008u;
    extern __shared__ char sm[];
    const uint32_t smb = smem_u32(sm);
    const int tid = threadIdx.x, lane = tid & 31, wid = tid >> 5;
    const int wm = wid & 1, wn = wid >> 1;
    const int bm = blockIdx.y * 128, bn = blockIdx.x * 128;

    float acc[4][4][4];
#pragma unroll
    for (int i = 0; i < 4; i++)
#pragma unroll
        for (int j = 0; j < 4; j++)
#pragma unroll
            for (int k = 0; k < 4; k++) acc[i][j][k] = 0.f;

    gemm_stage<USE_WL>(smb, Ah, Al, Wh, Wl, bm, bn, 0, tid);
    cp_commit();

#pragma unroll 1
    for (int c = 0; c < 16; c++) {
        const uint32_t bufb = (uint32_t)(c & 1) * BUFB;
        if (c < 15) {
            gemm_stage<USE_WL>(smb + (uint32_t)((c + 1) & 1) * BUFB,
                               Ah, Al, Wh, Wl, bm, bn, c + 1, tid);
            cp_commit();
            cp_wait<1>();
        } else {
            cp_wait<0>();
        }
        __syncthreads();

#pragma unroll
        for (int kc = 0; kc < 2; kc++) {
            uint32_t ah[4][4], al[4][4];
#pragma unroll
            for (int mt = 0; mt < 4; mt++) {
                const uint32_t aaddr = smb + bufb +
                    (uint32_t)((wm * 64 + mt * 16 + (lane & 15)) * GSTR +
                               kc * 16 + (lane >> 4) * 8) * 2;
                ldsm4(ah[mt], aaddr);
                ldsm4(al[mt], aaddr + 14336u);
            }
#pragma unroll
            for (int np = 0; np < 2; np++) {
                const uint32_t kaddr = smb + bufb + 28672u +
                    (uint32_t)((wn * 32 + np * 16 + (lane & 7) + ((lane & 16) ? 8 : 0)) * GSTR +
                               kc * 16 + ((lane & 8) ? 8 : 0)) * 2;
                uint32_t bh[4], bl[4];
                ldsm4(bh, kaddr);
                if (USE_WL) ldsm4(bl, kaddr + 14336u);
#pragma unroll
                for (int mt = 0; mt < 4; mt++) {
                    mma_f16(acc[mt][2 * np], ah[mt], bh[0], bh[1]);
                    mma_f16(acc[mt][2 * np], al[mt], bh[0], bh[1]);
                    mma_f16(acc[mt][2 * np + 1], ah[mt], bh[2], bh[3]);
                    mma_f16(acc[mt][2 * np + 1], al[mt], bh[2], bh[3]);
                    if (USE_WL) {
                        mma_f16(acc[mt][2 * np], ah[mt], bl[0], bl[1]);
                        mma_f16(acc[mt][2 * np + 1], ah[mt], bl[2], bl[3]);
                    }
                }
            }
        }
        __syncthreads();
    }

    // epilogue
#pragma unroll
    for (int nt = 0; nt < 4; nt++) {
        const int col = bn + wn * 32 + nt * 8 + 2 * (lane & 3);
        const float b0 = __ldg(bias + col), b1 = __ldg(bias + col + 1);
#pragma unroll
        for (int mt = 0; mt < 4; mt++) {
            const int row = bm + wm * 64 + mt * 16 + (lane >> 2);
            if (SPLIT_OUT) {
                const float f0 = (acc[mt][nt][0] + b0) * scale;
                const float f1 = (acc[mt][nt][1] + b1) * scale;
                const float f2 = (acc[mt][nt][2] + b0) * scale;
                const float f3 = (acc[mt][nt][3] + b1) * scale;
                __half2 h01 = __floats2half2_rn(f0, f1);
                __half2 h23 = __floats2half2_rn(f2, f3);
                float2 a01 = __half22float2(h01), a23 = __half22float2(h23);
                __half2 l01 = __floats2half2_rn(f0 - a01.x, f1 - a01.y);
                __half2 l23 = __floats2half2_rn(f2 - a23.x, f3 - a23.y);
                *(__half2*)(Oh + (size_t)row * 512 + col) = h01;
                *(__half2*)(Ol + (size_t)row * 512 + col) = l01;
                *(__half2*)(Oh + (size_t)(row + 8) * 512 + col) = h23;
                *(__half2*)(Ol + (size_t)(row + 8) * 512 + col) = l23;
            } else {
                float2 v0 = {acc[mt][nt][0] + b0, acc[mt][nt][1] + b1};
                float2 v1 = {acc[mt][nt][2] + b0, acc[mt][nt][3] + b1};
                *(float2*)(Of + (size_t)row * 512 + col) = v0;
                *(float2*)(Of + (size_t)(row + 8) * 512 + col) = v1;
            }
        }
    }
}

// ===========================================================================
// Tensor-core causal flash attention.
// QK^T: 2-product (Q hi+lo split x K-hi). PV: 1-product (P x V-hi).
// BQ=128, BK=64, 256 thr (8 warps x 16 rows). Q pre-scaled by SCL upstream.
// smem: QH 0 (18432), QL 18432; KV stage s at 36864+s*18432:
//       KH +0, VH +9216. Total 73728.
// ===========================================================================
#define ASTR 72
#define AKV0 36864u
#define AKVS 18432u
#define ATTN_SMEM 73728

__device__ __forceinline__ void attn_stage_kv(
    uint32_t sbase, const __half* Kh, const __half* Vh,
    size_t baseKV, int k0, int tid)
{
    // 1024 cp16: 2 arrays x 64 rows x 8 segs (row = 64 halves = 8 x 16B)
#pragma unroll
    for (int i = 0; i < 4; i++) {
        const int idx = tid + i * 256;       // 0..1023
        const int arr = idx >> 9;            // 0:Kh 1:Vh
        const int r = (idx >> 3) & 63;
        const int seg = idx & 7;
        const __half* base = arr ? Vh : Kh;
        const __half* src = base + baseKV + (size_t)(k0 + r) * 512 + seg * 8;
        const uint32_t dst = sbase + (uint32_t)arr * 9216u +
                             (uint32_t)(r * ASTR + seg * 8) * 2;
        cp16(dst, src);
    }
}

__global__ __launch_bounds__(256, 2) void attn_tc(
    const __half* __restrict__ Qh, const __half* __restrict__ Ql,
    const __half* __restrict__ Kh, const __half* __restrict__ Vh,
    __half* __restrict__ Oh, __half* __restrict__ Ol)
{
    extern __shared__ char sm[];
    const uint32_t smb = smem_u32(sm);
    const int tid = threadIdx.x, lane = tid & 31, wid = tid >> 5;
    const int qb = (gridDim.x - 1) - blockIdx.x;   // long blocks first
    const int hd = blockIdx.y, b = blockIdx.z;
    const int q0 = qb * 128;
    const size_t baseQ = ((size_t)b * SS + q0) * DD + hd * DH;
    const size_t baseKV = ((size_t)b * SS) * DD + hd * DH;
    const int row0 = wid * 16;

    // stage Q (hi/lo): 2048 cp16 = 2 arrays x 128 rows x 8 segs
#pragma unroll
    for (int i = 0; i < 8; i++) {
        const int idx = tid + i * 256;       // 0..2047
        const int arr = idx >> 10;           // 0:Qh 1:Ql
        const int r = (idx >> 3) & 127;
        const int seg = idx & 7;
        const __half* src = (arr ? Ql : Qh) + baseQ + (size_t)r * 512 + seg * 8;
        const uint32_t dst = smb + (uint32_t)arr * 18432u +
                             (uint32_t)(r * ASTR + seg * 8) * 2;
        cp16(dst, src);
    }
    attn_stage_kv(smb + AKV0, Kh, Vh, baseKV, 0, tid);
    cp_commit();

    float o[8][4];
#pragma unroll
    for (int i = 0; i < 8; i++)
#pragma unroll
        for (int j = 0; j < 4; j++) o[i][j] = 0.f;
    float m0 = -1e30f, m1 = -1e30f, l0 = 0.f, l1 = 0.f;

    const int kbmax = 2 * qb + 1;
#pragma unroll 1
    for (int kb = 0; kb <= kbmax; kb++) {
        const int k0 = kb * 64;
        const uint32_t kvb = smb + AKV0 + (uint32_t)(kb & 1) * AKVS;
        if (kb < kbmax) {
            attn_stage_kv(smb + AKV0 + (uint32_t)((kb + 1) & 1) * AKVS,
                          Kh, Vh, baseKV, k0 + 64, tid);
            cp_commit();
            cp_wait<1>();
        } else {
            cp_wait<0>();
        }
        __syncthreads();

        // ---- scores S = (Qh+Ql) Kh^T (2-product) ----
        float s[8][4];
#pragma unroll
        for (int i = 0; i < 8; i++)
#pragma unroll
            for (int j = 0; j < 4; j++) s[i][j] = 0.f;
#pragma unroll
        for (int kc = 0; kc < 4; kc++) {
            uint32_t qfh[4], qfl[4];
            const uint32_t qaddr = smb +
                (uint32_t)((row0 + (lane & 15)) * ASTR + kc * 16 + (lane >> 4) * 8) * 2;
            ldsm4(qfh, qaddr);
            ldsm4(qfl, qaddr + 18432u);
#pragma unroll
            for (int np = 0; np < 4; np++) {
                const uint32_t kaddr = kvb +
                    (uint32_t)((np * 16 + (lane & 7) + ((lane & 16) ? 8 : 0)) * ASTR +
                               kc * 16 + ((lane & 8) ? 8 : 0)) * 2;
                uint32_t bh[4];
                ldsm4(bh, kaddr);
                mma_f16(s[2 * np], qfh, bh[0], bh[1]);
                mma_f16(s[2 * np], qfl, bh[0], bh[1]);
                mma_f16(s[2 * np + 1], qfh, bh[2], bh[3]);
                mma_f16(s[2 * np + 1], qfl, bh[2], bh[3]);
            }
        }

        // ---- causal mask ----
        if (kb >= 2 * qb) {
            const int qr = q0 + row0 + (lane >> 2);
#pragma unroll
            for (int nt = 0; nt < 8; nt++) {
                const int cc = k0 + nt * 8 + 2 * (lane & 3);
                if (cc > qr)         s[nt][0] = -1e30f;
                if (cc + 1 > qr)     s[nt][1] = -1e30f;
                if (cc > qr + 8)     s[nt][2] = -1e30f;
                if (cc + 1 > qr + 8) s[nt][3] = -1e30f;
            }
        }

        // ---- online softmax on fragments (log2 domain) ----
        float mx0 = -1e30f, mx1 = -1e30f;
#pragma unroll
        for (int nt = 0; nt < 8; nt++) {
            mx0 = fmaxf(mx0, fmaxf(s[nt][0], s[nt][1]));
            mx1 = fmaxf(mx1, fmaxf(s[nt][2], s[nt][3]));
        }
        mx0 = fmaxf(mx0, __shfl_xor_sync(0xffffffffu, mx0, 1));
        mx0 = fmaxf(mx0, __shfl_xor_sync(0xffffffffu, mx0, 2));
        mx1 = fmaxf(mx1, __shfl_xor_sync(0xffffffffu, mx1, 1));
        mx1 = fmaxf(mx1, __shfl_xor_sync(0xffffffffu, mx1, 2));
        const float mn0 = fmaxf(m0, mx0), mn1 = fmaxf(m1, mx1);
        const float a0 = fexp2(m0 - mn0), a1 = fexp2(m1 - mn1);
        m0 = mn0; m1 = mn1;
        float rs0 = 0.f, rs1 = 0.f;
#pragma unroll
        for (int nt = 0; nt < 8; nt++) {
            s[nt][0] = fexp2(s[nt][0] - mn0);
            s[nt][1] = fexp2(s[nt][1] - mn0);
            s[nt][2] = fexp2(s[nt][2] - mn1);
            s[nt][3] = fexp2(s[nt][3] - mn1);
            rs0 += s[nt][0] + s[nt][1];
            rs1 += s[nt][2] + s[nt][3];
        }
        rs0 += __shfl_xor_sync(0xffffffffu, rs0, 1);
        rs0 += __shfl_xor_sync(0xffffffffu, rs0, 2);
        rs1 += __shfl_xor_sync(0xffffffffu, rs1, 1);
        rs1 += __shfl_xor_sync(0xffffffffu, rs1, 2);
        l0 = l0 * a0 + rs0;
        l1 = l1 * a1 + rs1;
#pragma unroll
        for (int nt = 0; nt < 8; nt++) {
            o[nt][0] *= a0; o[nt][1] *= a0;
            o[nt][2] *= a1; o[nt][3] *= a1;
        }

        // ---- PV: P x V-hi (1-product) ----
#pragma unroll
        for (int kc = 0; kc < 4; kc++) {
            uint32_t pa[4];
            pa[0] = h2u(__floats2half2_rn(s[2 * kc][0], s[2 * kc][1]));
            pa[1] = h2u(__floats2half2_rn(s[2 * kc][2], s[2 * kc][3]));
            pa[2] = h2u(__floats2half2_rn(s[2 * kc + 1][0], s[2 * kc + 1][1]));
            pa[3] = h2u(__floats2half2_rn(s[2 * kc + 1][2], s[2 * kc + 1][3]));
#pragma unroll
            for (int np = 0; np < 4; np++) {
                const uint32_t vaddr = kvb + 9216u +
                    (uint32_t)((kc * 16 + (lane & 15)) * ASTR + np * 16 + (lane >> 4) * 8) * 2;
                uint32_t vfh[4];
                ldsm4t(vfh, vaddr);
                mma_f16(o[2 * np], pa, vfh[0], vfh[1]);
                mma_f16(o[2 * np + 1], pa, vfh[2], vfh[3]);
            }
        }
        __syncthreads();
    }

    // epilogue: normalize, split-fp16 out (feeds O-projection GEMM)
    const float i0 = 1.f / l0, i1 = 1.f / l1;
    const int r0 = q0 + row0 + (lane >> 2);
#pragma unroll
    for (int nt = 0; nt < 8; nt++) {
        const int d = nt * 8 + 2 * (lane & 3);
        const float f0 = o[nt][0] * i0, f1 = o[nt][1] * i0;
        const float f2 = o[nt][2] * i1, f3 = o[nt][3] * i1;
        __half2 h01 = __floats2half2_rn(f0, f1);
        __half2 h23 = __floats2half2_rn(f2, f3);
        float2 a01 = __half22float2(h01), a23 = __half22float2(h23);
        __half2 l01 = __floats2half2_rn(f0 - a01.x, f1 - a01.y);
        __half2 l23 = __floats2half2_rn(f2 - a23.x, f3 - a23.y);
        const size_t off0 = ((size_t)b * SS + r0) * DD + hd * DH + d;
        const size_t off1 = ((size_t)b * SS + r0 + 8) * DD + hd * DH + d;
        *(__half2*)(Oh + off0) = h01;
        *(__half2*)(Ol + off0) = l01;
        *(__half2*)(Oh + off1) = h23;
        *(__half2*)(Ol + off1) = l23;
    }
}

// ===========================================================================
extern "C" void kernel_launch(void* const* d_in, const int* in_sizes, int n_in,
                              void* d_out, int out_size)
{
    const float* x  = (const float*)d_in[0];
    // d_in[1] = causal mask (implicit)
    const float* WQ = (const float*)d_in[2];
    const float* bQ = (const float*)d_in[3];
    const float* WK = (const float*)d_in[4];
    const float* bK = (const float*)d_in[5];
    const float* WV = (const float*)d_in[6];
    const float* bV = (const float*)d_in[7];
    const float* WO = (const float*)d_in[8];
    const float* bO = (const float*)d_in[9];
    float* out = (float*)d_out;

    __half *xh, *xl, *qh, *ql, *kh, *kl, *vh, *vl, *ah, *al;
    __half *wqh, *wql, *wkh, *wkl, *wvh, *wvl, *woh, *wol;
    cudaGetSymbolAddress((void**)&xh, g_xh);  cudaGetSymbolAddress((void**)&xl, g_xl);
    cudaGetSymbolAddress((void**)&qh, g_qh);  cudaGetSymbolAddress((void**)&ql, g_ql);
    cudaGetSymbolAddress((void**)&kh, g_kh);  cudaGetSymbolAddress((void**)&kl, g_kl);
    cudaGetSymbolAddress((void**)&vh, g_vh);  cudaGetSymbolAddress((void**)&vl, g_vl);
    cudaGetSymbolAddress((void**)&ah, g_ah);  cudaGetSymbolAddress((void**)&al, g_al);
    cudaGetSymbolAddress((void**)&wqh, g_wqh); cudaGetSymbolAddress((void**)&wql, g_wql);
    cudaGetSymbolAddress((void**)&wkh, g_wkh); cudaGetSymbolAddress((void**)&wkl, g_wkl);
    cudaGetSymbolAddress((void**)&wvh, g_wvh); cudaGetSymbolAddress((void**)&wvl, g_wvl);
    cudaGetSymbolAddress((void**)&woh, g_woh); cudaGetSymbolAddress((void**)&wol, g_wol);

    const int GEMM_SMEM3 = 2 * 57344;   // 3-product (O projection)
    const int GEMM_SMEM2 = 2 * 43008;   // 2-product (QKV projections)
    cudaFuncSetAttribute((const void*)gemm16<true, false>,
                         cudaFuncAttributeMaxDynamicSharedMemorySize, GEMM_SMEM2);
    cudaFuncSetAttribute((const void*)gemm16<false, true>,
                         cudaFuncAttributeMaxDynamicSharedMemorySize, GEMM_SMEM3);
    cudaFuncSetAttribute((const void*)attn_tc,
                         cudaFuncAttributeMaxDynamicSharedMemorySize, ATTN_SMEM);

    const int ntot = N4X + 4 * N4W;
    split_all<<<(ntot + 255) / 256, 256>>>(x, WQ, WK, WV, WO,
                                           xh, xl, wqh, wql, wkh, wkl,
                                           wvh, wvl, woh, wol);

    dim3 gg(DD / 128, MTOT / 128);   // (4, 64)
    gemm16<true, false><<<gg, 256, GEMM_SMEM2>>>(xh, xl, wqh, wql, bQ, SCL,
                                                 qh, ql, nullptr);
    gemm16<true, false><<<gg, 256, GEMM_SMEM2>>>(xh, xl, wkh, wkl, bK, 1.f,
                                                 kh, kl, nullptr);
    gemm16<true, false><<<gg, 256, GEMM_SMEM2>>>(xh, xl, wvh, wvl, bV, 1.f,
                                                 vh, vl, nullptr);
    attn_tc<<<dim3(SS / 128, HH, BB), 256, ATTN_SMEM>>>(qh, ql, kh, vh, ah, al);
    gemm16<false, true><<<gg, 256, GEMM_SMEM3>>>(ah, al, woh, wol, bO, 1.f,
                                                 nullptr, nullptr, out);
}

// round 16
// speedup vs baseline: 1.6159x; 1.1762x over previous
#include <cuda_runtime.h>
#include <cuda_fp16.h>
#include <cstdint>
#include <cstddef>

#define BB 4
#define SS 2048
#define DD 512
#define HH 8
#define DH 64
#define MTOT (BB * SS)

// softmax scale folded with log2(e): scores_log2 = (Q*SCL) . K
#define SCL 0.18033688011112042f   // (1/8) * log2(e)

// ---------------------------------------------------------------------------
// Scratch (allocation-free rule: __device__ globals). fp16 split pairs.
// ---------------------------------------------------------------------------
__device__ __half g_xh[MTOT * DD], g_xl[MTOT * DD];
__device__ __half g_qh[MTOT * DD], g_ql[MTOT * DD];
__device__ __half g_kh[MTOT * DD];
__device__ __half g_vh[MTOT * DD];
__device__ __half g_ah[MTOT * DD], g_al[MTOT * DD];
__device__ __half g_wqh[DD * DD], g_wql[DD * DD];
__device__ __half g_wkh[DD * DD], g_wkl[DD * DD];
__device__ __half g_wvh[DD * DD], g_wvl[DD * DD];
__device__ __half g_woh[DD * DD], g_wol[DD * DD];

// ===========================================================================
// helpers
// ===========================================================================
__device__ __forceinline__ uint32_t smem_u32(const void* p) {
    uint32_t a;
    asm("{ .reg .u64 t; cvta.to.shared.u64 t, %1; cvt.u32.u64 %0, t; }"
        : "=r"(a) : "l"(p));
    return a;
}

__device__ __forceinline__ void ldsm4(uint32_t* r, uint32_t addr) {
    asm volatile("ldmatrix.sync.aligned.m8n8.x4.shared.b16 {%0,%1,%2,%3}, [%4];"
        : "=r"(r[0]), "=r"(r[1]), "=r"(r[2]), "=r"(r[3]) : "r"(addr));
}
__device__ __forceinline__ void ldsm4t(uint32_t* r, uint32_t addr) {
    asm volatile("ldmatrix.sync.aligned.m8n8.x4.trans.shared.b16 {%0,%1,%2,%3}, [%4];"
        : "=r"(r[0]), "=r"(r[1]), "=r"(r[2]), "=r"(r[3]) : "r"(addr));
}

__device__ __forceinline__ void mma_f16(float* c, const uint32_t* a,
                                        uint32_t b0, uint32_t b1) {
    asm volatile(
        "mma.sync.aligned.m16n8k16.row.col.f32.f16.f16.f32 "
        "{%0,%1,%2,%3}, {%4,%5,%6,%7}, {%8,%9}, {%0,%1,%2,%3};"
        : "+f"(c[0]), "+f"(c[1]), "+f"(c[2]), "+f"(c[3])
        : "r"(a[0]), "r"(a[1]), "r"(a[2]), "r"(a[3]), "r"(b0), "r"(b1));
}

__device__ __forceinline__ void cp16(uint32_t dst, const void* src) {
    asm volatile("cp.async.cg.shared.global [%0], [%1], 16;"
                 :: "r"(dst), "l"(src));
}
__device__ __forceinline__ void cp_commit() {
    asm volatile("cp.async.commit_group;" ::: "memory");
}
template <int N>
__device__ __forceinline__ void cp_wait() {
    asm volatile("cp.async.wait_group %0;" :: "n"(N) : "memory");
}

__device__ __forceinline__ uint32_t h2u(__half2 h) {
    return *reinterpret_cast<uint32_t*>(&h);
}

// 2^x via degree-4 poly on FMA pipe.
__device__ __forceinline__ float fexp2(float x) {
    x = fmaxf(x, -125.0f);
    float n = rintf(x);
    float f = x - n;
    float p = 0.00961812910f;
    p = fmaf(p, f, 0.0555041087f);
    p = fmaf(p, f, 0.240226507f);
    p = fmaf(p, f, 0.693147180f);
    p = fmaf(p, f, 1.0f);
    int e = (int)n;
    return p * __int_as_float((e + 127) << 23);
}

// ===========================================================================
// prep: fp32 -> (hi, lo) fp16 split for x + all 4 weights, one launch
// ===========================================================================
#define N4X (MTOT * DD / 4)
#define N4W (DD * DD / 4)

__global__ void split_all(
    const float* __restrict__ x,
    const float* __restrict__ WQ, const float* __restrict__ WK,
    const float* __restrict__ WV, const float* __restrict__ WO,
    __half* __restrict__ xh, __half* __restrict__ xl,
    __half* __restrict__ wqh, __half* __restrict__ wql,
    __half* __restrict__ wkh, __half* __restrict__ wkl,
    __half* __restrict__ wvh, __half* __restrict__ wvl,
    __half* __restrict__ woh, __half* __restrict__ wol)
{
    const int i = blockIdx.x * blockDim.x + threadIdx.x;
    const float* src;
    __half *hi, *lo;
    int off;
    if (i < N4X) {
        src = x; hi = xh; lo = xl; off = i;
    } else {
        const int j = i - N4X;
        const int w = j >> 16;            // N4W == 65536
        off = j & 65535;
        if (w == 0)      { src = WQ; hi = wqh; lo = wql; }
        else if (w == 1) { src = WK; hi = wkh; lo = wkl; }
        else if (w == 2) { src = WV; hi = wvh; lo = wvl; }
        else             { src = WO; hi = woh; lo = wol; }
    }
    float4 v = ((const float4*)src)[off];
    __half2 a = __floats2half2_rn(v.x, v.y);
    __half2 b = __floats2half2_rn(v.z, v.w);
    float2 fa = __half22float2(a), fb = __half22float2(b);
    __half2 la = __floats2half2_rn(v.x - fa.x, v.y - fa.y);
    __half2 lb = __floats2half2_rn(v.z - fb.x, v.w - fb.y);
    ((__half2*)hi)[2 * off] = a;  ((__half2*)hi)[2 * off + 1] = b;
    ((__half2*)lo)[2 * off] = la; ((__half2*)lo)[2 * off + 1] = lb;
}

// ===========================================================================
// Split-fp16 tensor GEMM, cp.async double buffer.
// C[M,N] = A@W^T + bias. CTA 128x128, chunk 32, 256 thr (2x4 warps, 64x32).
// ASPL: include Al*Wh term. WSPL: include Ah*Wl term.
// QKV: <false,false> plain fp16 (2 regions). O-proj: <true,true> 3-product.
// Region stride 14336 (128 rows x 56 halves); buffer = nregions*14336.
// ===========================================================================
#define GSTR 56

template <bool ASPL, bool WSPL>
__device__ __forceinline__ void gemm_stage(
    uint32_t sbase, const __half* Ah, const __half* Al,
    const __half* Wh, const __half* Wl, int bm, int bn, int c, int tid)
{
    constexpr int NREG = 2 + (ASPL ? 1 : 0) + (WSPL ? 1 : 0);
#pragma unroll
    for (int i = 0; i < NREG * 2; i++) {
        const int idx = tid + i * 256;
        const int reg = idx >> 9;
        const int r = (idx >> 2) & 127;
        const int seg = idx & 3;
        const __half* base;
        int rowb;
        if (reg == 0)                      { base = Ah; rowb = bm; }
        else if (ASPL && reg == 1)         { base = Al; rowb = bm; }
        else if (reg == 1 + (ASPL ? 1 : 0)){ base = Wh; rowb = bn; }
        else                               { base = Wl; rowb = bn; }
        const __half* src = base + (size_t)(rowb + r) * 512 + c * 32 + seg * 8;
        const uint32_t dst = sbase + (uint32_t)reg * 14336u +
                             (uint32_t)(r * GSTR + seg * 8) * 2;
        cp16(dst, src);
    }
}

template <bool SPLIT_OUT, bool ASPL, bool WSPL>
__global__ __launch_bounds__(256, 2) void gemm16(
    const __half* __restrict__ Ah, const __half* __restrict__ Al,
    const __half* __restrict__ Wh, const __half* __restrict__ Wl,
    const float* __restrict__ bias, float scale,
    __half* __restrict__ Oh, __half* __restrict__ Ol,
    float* __restrict__ Of)
{
    constexpr uint32_t BUFB =
        (uint32_t)(2 + (ASPL ? 1 : 0) + (WSPL ? 1 : 0)) * 14336u;
    constexpr uint32_t WHOFF = (uint32_t)(1 + (ASPL ? 1 : 0)) * 14336u;
    extern __shared__ char sm[];
    const uint32_t smb = smem_u32(sm);
    const int tid = threadIdx.x, lane = tid & 31, wid = tid >> 5;
    const int wm = wid & 1, wn = wid >> 1;
    const int bm = blockIdx.y * 128, bn = blockIdx.x * 128;

    float acc[4][4][4];
#pragma unroll
    for (int i = 0; i < 4; i++)
#pragma unroll
        for (int j = 0; j < 4; j++)
#pragma unroll
            for (int k = 0; k < 4; k++) acc[i][j][k] = 0.f;

    gemm_stage<ASPL, WSPL>(smb, Ah, Al, Wh, Wl, bm, bn, 0, tid);
    cp_commit();

#pragma unroll 1
    for (int c = 0; c < 16; c++) {
        const uint32_t bufb = (uint32_t)(c & 1) * BUFB;
        if (c < 15) {
            gemm_stage<ASPL, WSPL>(smb + (uint32_t)((c + 1) & 1) * BUFB,
                                   Ah, Al, Wh, Wl, bm, bn, c + 1, tid);
            cp_commit();
            cp_wait<1>();
        } else {
            cp_wait<0>();
        }
        __syncthreads();

#pragma unroll
        for (int kc = 0; kc < 2; kc++) {
            uint32_t ah[4][4], al[4][4];
#pragma unroll
            for (int mt = 0; mt < 4; mt++) {
                const uint32_t aaddr = smb + bufb +
                    (uint32_t)((wm * 64 + mt * 16 + (lane & 15)) * GSTR +
                               kc * 16 + (lane >> 4) * 8) * 2;
                ldsm4(ah[mt], aaddr);
                if (ASPL) ldsm4(al[mt], aaddr + 14336u);
            }
#pragma unroll
            for (int np = 0; np < 2; np++) {
                const uint32_t kaddr = smb + bufb + WHOFF +
                    (uint32_t)((wn * 32 + np * 16 + (lane & 7) + ((lane & 16) ? 8 : 0)) * GSTR +
                               kc * 16 + ((lane & 8) ? 8 : 0)) * 2;
                uint32_t bh[4], bl[4];
                ldsm4(bh, kaddr);
                if (WSPL) ldsm4(bl, kaddr + 14336u);
#pragma unroll
                for (int mt = 0; mt < 4; mt++) {
                    mma_f16(acc[mt][2 * np], ah[mt], bh[0], bh[1]);
                    mma_f16(acc[mt][2 * np + 1], ah[mt], bh[2], bh[3]);
                    if (ASPL) {
                        mma_f16(acc[mt][2 * np], al[mt], bh[0], bh[1]);
                        mma_f16(acc[mt][2 * np + 1], al[mt], bh[2], bh[3]);
                    }
                    if (WSPL) {
                        mma_f16(acc[mt][2 * np], ah[mt], bl[0], bl[1]);
                        mma_f16(acc[mt][2 * np + 1], ah[mt], bl[2], bl[3]);
                    }
                }
            }
        }
        __syncthreads();
    }

    // epilogue
#pragma unroll
    for (int nt = 0; nt < 4; nt++) {
        const int col = bn + wn * 32 + nt * 8 + 2 * (lane & 3);
        const float b0 = __ldg(bias + col), b1 = __ldg(bias + col + 1);
#pragma unroll
        for (int mt = 0; mt < 4; mt++) {
            const int row = bm + wm * 64 + mt * 16 + (lane >> 2);
            if (SPLIT_OUT) {
                const float f0 = (acc[mt][nt][0] + b0) * scale;
                const float f1 = (acc[mt][nt][1] + b1) * scale;
                const float f2 = (acc[mt][nt][2] + b0) * scale;
                const float f3 = (acc[mt][nt][3] + b1) * scale;
                __half2 h01 = __floats2half2_rn(f0, f1);
                __half2 h23 = __floats2half2_rn(f2, f3);
                *(__half2*)(Oh + (size_t)row * 512 + col) = h01;
                *(__half2*)(Oh + (size_t)(row + 8) * 512 + col) = h23;
                if (Ol) {
                    float2 a01 = __half22float2(h01), a23 = __half22float2(h23);
                    __half2 l01 = __floats2half2_rn(f0 - a01.x, f1 - a01.y);
                    __half2 l23 = __floats2half2_rn(f2 - a23.x, f3 - a23.y);
                    *(__half2*)(Ol + (size_t)row * 512 + col) = l01;
                    *(__half2*)(Ol + (size_t)(row + 8) * 512 + col) = l23;
                }
            } else {
                float2 v0 = {acc[mt][nt][0] + b0, acc[mt][nt][1] + b1};
                float2 v1 = {acc[mt][nt][2] + b0, acc[mt][nt][3] + b1};
                *(float2*)(Of + (size_t)row * 512 + col) = v0;
                *(float2*)(Of + (size_t)(row + 8) * 512 + col) = v1;
            }
        }
    }
}

// ===========================================================================
// Tensor-core causal flash attention.
// QK^T: 2-product (Q hi+lo split x K-hi). PV: 1-product (P x V-hi).
// BQ=128, BK=64, 256 thr (8 warps x 16 rows). Q pre-scaled by SCL upstream.
// smem: QH 0 (18432), QL 18432; KV stage s at 36864+s*18432:
//       KH +0, VH +9216. Total 73728.
// ===========================================================================
#define ASTR 72
#define AKV0 36864u
#define AKVS 18432u
#define ATTN_SMEM 73728

__device__ __forceinline__ void attn_stage_kv(
    uint32_t sbase, const __half* Kh, const __half* Vh,
    size_t baseKV, int k0, int tid)
{
    // 1024 cp16: 2 arrays x 64 rows x 8 segs (row = 64 halves = 8 x 16B)
#pragma unroll
    for (int i = 0; i < 4; i++) {
        const int idx = tid + i * 256;       // 0..1023
        const int arr = idx >> 9;            // 0:Kh 1:Vh
        const int r = (idx >> 3) & 63;
        const int seg = idx & 7;
        const __half* base = arr ? Vh : Kh;
        const __half* src = base + baseKV + (size_t)(k0 + r) * 512 + seg * 8;
        const uint32_t dst = sbase + (uint32_t)arr * 9216u +
                             (uint32_t)(r * ASTR + seg * 8) * 2;
        cp16(dst, src);
    }
}

__global__ __launch_bounds__(256, 2) void attn_tc(
    const __half* __restrict__ Qh, const __half* __restrict__ Ql,
    const __half* __restrict__ Kh, const __half* __restrict__ Vh,
    __half* __restrict__ Oh, __half* __restrict__ Ol)
{
    extern __shared__ char sm[];
    const uint32_t smb = smem_u32(sm);
    const int tid = threadIdx.x, lane = tid & 31, wid = tid >> 5;
    const int qb = (gridDim.x - 1) - blockIdx.x;   // long blocks first
    const int hd = blockIdx.y, b = blockIdx.z;
    const int q0 = qb * 128;
    const size_t baseQ = ((size_t)b * SS + q0) * DD + hd * DH;
    const size_t baseKV = ((size_t)b * SS) * DD + hd * DH;
    const int row0 = wid * 16;

    // stage Q (hi/lo): 2048 cp16 = 2 arrays x 128 rows x 8 segs
#pragma unroll
    for (int i = 0; i < 8; i++) {
        const int idx = tid + i * 256;       // 0..2047
        const int arr = idx >> 10;           // 0:Qh 1:Ql
        const int r = (idx >> 3) & 127;
        const int seg = idx & 7;
        const __half* src = (arr ? Ql : Qh) + baseQ + (size_t)r * 512 + seg * 8;
        const uint32_t dst = smb + (uint32_t)arr * 18432u +
                             (uint32_t)(r * ASTR + seg * 8) * 2;
        cp16(dst, src);
    }
    attn_stage_kv(smb + AKV0, Kh, Vh, baseKV, 0, tid);
    cp_commit();

    float o[8][4];
#pragma unroll
    for (int i = 0; i < 8; i++)
#pragma unroll
        for (int j = 0; j < 4; j++) o[i][j] = 0.f;
    float m0 = -1e30f, m1 = -1e30f, l0 = 0.f, l1 = 0.f;

    const int kbmax = 2 * qb + 1;
#pragma unroll 1
    for (int kb = 0; kb <= kbmax; kb++) {
        const int k0 = kb * 64;
        const uint32_t kvb = smb + AKV0 + (uint32_t)(kb & 1) * AKVS;
        if (kb < kbmax) {
            attn_stage_kv(smb + AKV0 + (uint32_t)((kb + 1) & 1) * AKVS,
                          Kh, Vh, baseKV, k0 + 64, tid);
            cp_commit();
            cp_wait<1>();
        } else {
            cp_wait<0>();
        }
        __syncthreads();

        // ---- scores S = (Qh+Ql) Kh^T (2-product) ----
        float s[8][4];
#pragma unroll
        for (int i = 0; i < 8; i++)
#pragma unroll
            for (int j = 0; j < 4; j++) s[i][j] = 0.f;
#pragma unroll
        for (int kc = 0; kc < 4; kc++) {
            uint32_t qfh[4], qfl[4];
            const uint32_t qaddr = smb +
                (uint32_t)((row0 + (lane & 15)) * ASTR + kc * 16 + (lane >> 4) * 8) * 2;
            ldsm4(qfh, qaddr);
            ldsm4(qfl, qaddr + 18432u);
#pragma unroll
            for (int np = 0; np < 4; np++) {
                const uint32_t kaddr = kvb +
                    (uint32_t)((np * 16 + (lane & 7) + ((lane & 16) ? 8 : 0)) * ASTR +
                               kc * 16 + ((lane & 8) ? 8 : 0)) * 2;
                uint32_t bh[4];
                ldsm4(bh, kaddr);
                mma_f16(s[2 * np], qfh, bh[0], bh[1]);
                mma_f16(s[2 * np], qfl, bh[0], bh[1]);
                mma_f16(s[2 * np + 1], qfh, bh[2], bh[3]);
                mma_f16(s[2 * np + 1], qfl, bh[2], bh[3]);
            }
        }

        // ---- causal mask ----
        if (kb >= 2 * qb) {
            const int qr = q0 + row0 + (lane >> 2);
#pragma unroll
            for (int nt = 0; nt < 8; nt++) {
                const int cc = k0 + nt * 8 + 2 * (lane & 3);
                if (cc > qr)         s[nt][0] = -1e30f;
                if (cc + 1 > qr)     s[nt][1] = -1e30f;
                if (cc > qr + 8)     s[nt][2] = -1e30f;
                if (cc + 1 > qr + 8) s[nt][3] = -1e30f;
            }
        }

        // ---- online softmax on fragments (log2 domain) ----
        float mx0 = -1e30f, mx1 = -1e30f;
#pragma unroll
        for (int nt = 0; nt < 8; nt++) {
            mx0 = fmaxf(mx0, fmaxf(s[nt][0], s[nt][1]));
            mx1 = fmaxf(mx1, fmaxf(s[nt][2], s[nt][3]));
        }
        mx0 = fmaxf(mx0, __shfl_xor_sync(0xffffffffu, mx0, 1));
        mx0 = fmaxf(mx0, __shfl_xor_sync(0xffffffffu, mx0, 2));
        mx1 = fmaxf(mx1, __shfl_xor_sync(0xffffffffu, mx1, 1));
        mx1 = fmaxf(mx1, __shfl_xor_sync(0xffffffffu, mx1, 2));
        const float mn0 = fmaxf(m0, mx0), mn1 = fmaxf(m1, mx1);
        const float a0 = fexp2(m0 - mn0), a1 = fexp2(m1 - mn1);
        m0 = mn0; m1 = mn1;
        float rs0 = 0.f, rs1 = 0.f;
#pragma unroll
        for (int nt = 0; nt < 8; nt++) {
            s[nt][0] = fexp2(s[nt][0] - mn0);
            s[nt][1] = fexp2(s[nt][1] - mn0);
            s[nt][2] = fexp2(s[nt][2] - mn1);
            s[nt][3] = fexp2(s[nt][3] - mn1);
            rs0 += s[nt][0] + s[nt][1];
            rs1 += s[nt][2] + s[nt][3];
        }
        rs0 += __shfl_xor_sync(0xffffffffu, rs0, 1);
        rs0 += __shfl_xor_sync(0xffffffffu, rs0, 2);
        rs1 += __shfl_xor_sync(0xffffffffu, rs1, 1);
        rs1 += __shfl_xor_sync(0xffffffffu, rs1, 2);
        l0 = l0 * a0 + rs0;
        l1 = l1 * a1 + rs1;
#pragma unroll
        for (int nt = 0; nt < 8; nt++) {
            o[nt][0] *= a0; o[nt][1] *= a0;
            o[nt][2] *= a1; o[nt][3] *= a1;
        }

        // ---- PV: P x V-hi (1-product) ----
#pragma unroll
        for (int kc = 0; kc < 4; kc++) {
            uint32_t pa[4];
            pa[0] = h2u(__floats2half2_rn(s[2 * kc][0], s[2 * kc][1]));
            pa[1] = h2u(__floats2half2_rn(s[2 * kc][2], s[2 * kc][3]));
            pa[2] = h2u(__floats2half2_rn(s[2 * kc + 1][0], s[2 * kc + 1][1]));
            pa[3] = h2u(__floats2half2_rn(s[2 * kc + 1][2], s[2 * kc + 1][3]));
#pragma unroll
            for (int np = 0; np < 4; np++) {
                const uint32_t vaddr = kvb + 9216u +
                    (uint32_t)((kc * 16 + (lane & 15)) * ASTR + np * 16 + (lane >> 4) * 8) * 2;
                uint32_t vfh[4];
                ldsm4t(vfh, vaddr);
                mma_f16(o[2 * np], pa, vfh[0], vfh[1]);
                mma_f16(o[2 * np + 1], pa, vfh[2], vfh[3]);
            }
        }
        __syncthreads();
    }

    // epilogue: normalize, split-fp16 out (feeds O-projection GEMM)
    const float i0 = 1.f / l0, i1 = 1.f / l1;
    const int r0 = q0 + row0 + (lane >> 2);
#pragma unroll
    for (int nt = 0; nt < 8; nt++) {
        const int d = nt * 8 + 2 * (lane & 3);
        const float f0 = o[nt][0] * i0, f1 = o[nt][1] * i0;
        const float f2 = o[nt][2] * i1, f3 = o[nt][3] * i1;
        __half2 h01 = __floats2half2_rn(f0, f1);
        __half2 h23 = __floats2half2_rn(f2, f3);
        float2 a01 = __half22float2(h01), a23 = __half22float2(h23);
        __half2 l01 = __floats2half2_rn(f0 - a01.x, f1 - a01.y);
        __half2 l23 = __floats2half2_rn(f2 - a23.x, f3 - a23.y);
        const size_t off0 = ((size_t)b * SS + r0) * DD + hd * DH + d;
        const size_t off1 = ((size_t)b * SS + r0 + 8) * DD + hd * DH + d;
        *(__half2*)(Oh + off0) = h01;
        *(__half2*)(Ol + off0) = l01;
        *(__half2*)(Oh + off1) = h23;
        *(__half2*)(Ol + off1) = l23;
    }
}

// ===========================================================================
extern "C" void kernel_launch(void* const* d_in, const int* in_sizes, int n_in,
                              void* d_out, int out_size)
{
    const float* x  = (const float*)d_in[0];
    // d_in[1] = causal mask (implicit)
    const float* WQ = (const float*)d_in[2];
    const float* bQ = (const float*)d_in[3];
    const float* WK = (const float*)d_in[4];
    const float* bK = (const float*)d_in[5];
    const float* WV = (const float*)d_in[6];
    const float* bV = (const float*)d_in[7];
    const float* WO = (const float*)d_in[8];
    const float* bO = (const float*)d_in[9];
    float* out = (float*)d_out;

    __half *xh, *xl, *qh, *ql, *kh, *vh, *ah, *al;
    __half *wqh, *wql, *wkh, *wkl, *wvh, *wvl, *woh, *wol;
    cudaGetSymbolAddress((void**)&xh, g_xh);  cudaGetSymbolAddress((void**)&xl, g_xl);
    cudaGetSymbolAddress((void**)&qh, g_qh);  cudaGetSymbolAddress((void**)&ql, g_ql);
    cudaGetSymbolAddress((void**)&kh, g_kh);
    cudaGetSymbolAddress((void**)&vh, g_vh);
    cudaGetSymbolAddress((void**)&ah, g_ah);  cudaGetSymbolAddress((void**)&al, g_al);
    cudaGetSymbolAddress((void**)&wqh, g_wqh); cudaGetSymbolAddress((void**)&wql, g_wql);
    cudaGetSymbolAddress((void**)&wkh, g_wkh); cudaGetSymbolAddress((void**)&wkl, g_wkl);
    cudaGetSymbolAddress((void**)&wvh, g_wvh); cudaGetSymbolAddress((void**)&wvl, g_wvl);
    cudaGetSymbolAddress((void**)&woh, g_woh); cudaGetSymbolAddress((void**)&wol, g_wol);

    const int GEMM_SMEM_QKV = 2 * 28672;   // plain fp16, 2 regions/buffer
    const int GEMM_SMEM_O   = 2 * 57344;   // 3-product, 4 regions/buffer
    cudaFuncSetAttribute((const void*)gemm16<true, false, false>,
                         cudaFuncAttributeMaxDynamicSharedMemorySize, GEMM_SMEM_QKV);
    cudaFuncSetAttribute((const void*)gemm16<false, true, true>,
                         cudaFuncAttributeMaxDynamicSharedMemorySize, GEMM_SMEM_O);
    cudaFuncSetAttribute((const void*)attn_tc,
                         cudaFuncAttributeMaxDynamicSharedMemorySize, ATTN_SMEM);

    const int ntot = N4X + 4 * N4W;
    split_all<<<(ntot + 255) / 256, 256>>>(x, WQ, WK, WV, WO,
                                           xh, xl, wqh, wql, wkh, wkl,
                                           wvh, wvl, woh, wol);

    dim3 gg(DD / 128, MTOT / 128);   // (4, 64)
    gemm16<true, false, false><<<gg, 256, GEMM_SMEM_QKV>>>(
        xh, xl, wqh, wql, bQ, SCL, qh, ql, nullptr);
    gemm16<true, false, false><<<gg, 256, GEMM_SMEM_QKV>>>(
        xh, xl, wkh, wkl, bK, 1.f, kh, nullptr, nullptr);
    gemm16<true, false, false><<<gg, 256, GEMM_SMEM_QKV>>>(
        xh, xl, wvh, wvl, bV, 1.f, vh, nullptr, nullptr);
    attn_tc<<<dim3(SS / 128, HH, BB), 256, ATTN_SMEM>>>(qh, ql, kh, vh, ah, al);
    gemm16<false, true, true><<<gg, 256, GEMM_SMEM_O>>>(
        ah, al, woh, wol, bO, 1.f, nullptr, nullptr, out);
}